// round 1
// baseline (speedup 1.0000x reference)
#include <cuda_runtime.h>
#include <cstdint>
#include <cstddef>

// ---------------------------------------------------------------------------
// Problem constants (MambaVisionMixer, B=4, L=2048)
// ---------------------------------------------------------------------------
#define B_SZ    4
#define LSEQ    2048
#define DMODEL  1024
#define DINNER  2048
#define DHALF   1024
#define DSTATE  16
#define DTRANK  64
#define XDBL_N  96          // DT_RANK + 2*D_STATE
#define MROWS   (B_SZ*LSEQ) // 8192

// ---------------------------------------------------------------------------
// Device scratch (static __device__ arrays: allowed; no allocations)
// ---------------------------------------------------------------------------
__device__ float g_xz   [(size_t)MROWS * DINNER];  // 64 MB
__device__ float g_xs   [(size_t)MROWS * DHALF];   // 32 MB  (conv+silu of x-half)
__device__ float g_z    [(size_t)MROWS * DHALF];   // 32 MB  (conv+silu of z-half)
__device__ float g_xdbl [(size_t)MROWS * XDBL_N];  // 3 MB
__device__ float g_delta[(size_t)MROWS * DHALF];   // 32 MB
__device__ float g_y    [(size_t)MROWS * DHALF];   // 32 MB

// ---------------------------------------------------------------------------
// Packed f32x2 helpers (Blackwell packed-fp32 pipe; 2x FFMA throughput)
// ---------------------------------------------------------------------------
typedef unsigned long long ull_t;

__device__ __forceinline__ ull_t pack2(float a, float b) {
    ull_t r;
    asm("mov.b64 %0, {%1, %2};" : "=l"(r) : "f"(a), "f"(b));
    return r;
}
__device__ __forceinline__ void unpack2(ull_t v, float& a, float& b) {
    asm("mov.b64 {%0, %1}, %2;" : "=f"(a), "=f"(b) : "l"(v));
}
__device__ __forceinline__ ull_t fma2(ull_t a, ull_t b, ull_t c) {
    ull_t d;
    asm("fma.rn.f32x2 %0, %1, %2, %3;" : "=l"(d) : "l"(a), "l"(b), "l"(c));
    return d;
}

__device__ __forceinline__ float softplus_f(float x) {
    // logaddexp(x, 0) = max(x,0) + log1p(exp(-|x|))  (matches jax.nn.softplus)
    return fmaxf(x, 0.0f) + log1pf(expf(-fabsf(x)));
}
__device__ __forceinline__ float silu_f(float x) {
    return x / (1.0f + expf(-x));
}

// ---------------------------------------------------------------------------
// Main SGEMM (f32x2 packed):  C[M,N] = concat(A0|A1)[M,K] @ B[K,N] (+bias)(+softplus)
//   A is a logical row-major [M,K] matrix: columns [0,splitK) come from A0
//   (leading dim lda0), columns [splitK,K) from A1 (leading dim lda1).
//   BM=BN=128, BK=16, 256 threads, 8x8 outputs/thread as 32 f32x2 accumulators.
// ---------------------------------------------------------------------------
template <bool SOFTPLUS, bool HASBIAS>
__global__ __launch_bounds__(256, 2)
void sgemm_f32x2_kernel(const float* __restrict__ A0, int lda0, int splitK,
                        const float* __restrict__ A1, int lda1,
                        const float* __restrict__ Bg,
                        const float* __restrict__ bias, float bias_scale,
                        float* __restrict__ C,
                        int M, int N, int K)
{
    constexpr int BM = 128, BN = 128, BK = 16;
    __shared__ ull_t As2[BK][BM];   // A pre-duplicated (a,a) pairs, k-major
    __shared__ float Bs [BK][BN];

    const int tid    = threadIdx.x;
    const int rowBlk = blockIdx.y * BM;
    const int colBlk = blockIdx.x * BN;
    const int tRow   = tid >> 4;    // 0..15  -> 8 rows each
    const int tCol   = tid & 15;    // 0..15  -> 8 cols each

    ull_t acc[8][4];
    #pragma unroll
    for (int i = 0; i < 8; i++)
        #pragma unroll
        for (int j = 0; j < 4; j++) acc[i][j] = 0ull;

    // tile-load coordinates (2 slots of 256 threads each)
    //   A tile: 128 rows x 16 cols -> slot>>2 = row, (slot&3)*4 = col group
    //   B tile: 16 rows x 128 cols -> slot>>5 = row, (slot&31)*4 = col group
    float4 aReg[2], bReg[2];

    auto loadA4 = [&](int m, int kk) -> float4 {
        const float* p;
        if (kk < splitK) p = A0 + (size_t)m * lda0 + kk;
        else             p = A1 + (size_t)m * lda1 + (kk - splitK);
        return *reinterpret_cast<const float4*>(p);
    };

    const int nTiles = K / BK;

    // prefetch tile 0
    #pragma unroll
    for (int i = 0; i < 2; i++) {
        int slot = tid + i * 256;
        int aRow = slot >> 2, aCol = (slot & 3) * 4;
        aReg[i] = loadA4(rowBlk + aRow, aCol);
        int bRow = slot >> 5, bCol = (slot & 31) * 4;
        bReg[i] = *reinterpret_cast<const float4*>(Bg + (size_t)bRow * N + colBlk + bCol);
    }

    for (int t = 0; t < nTiles; ++t) {
        // commit prefetched regs -> smem
        #pragma unroll
        for (int i = 0; i < 2; i++) {
            int slot = tid + i * 256;
            int aRow = slot >> 2, aCol = (slot & 3) * 4;
            As2[aCol + 0][aRow] = pack2(aReg[i].x, aReg[i].x);
            As2[aCol + 1][aRow] = pack2(aReg[i].y, aReg[i].y);
            As2[aCol + 2][aRow] = pack2(aReg[i].z, aReg[i].z);
            As2[aCol + 3][aRow] = pack2(aReg[i].w, aReg[i].w);
            int bRow = slot >> 5, bCol = (slot & 31) * 4;
            *reinterpret_cast<float4*>(&Bs[bRow][bCol]) = bReg[i];
        }
        __syncthreads();

        // prefetch next tile (overlaps with compute below)
        if (t + 1 < nTiles) {
            int k0 = (t + 1) * BK;
            #pragma unroll
            for (int i = 0; i < 2; i++) {
                int slot = tid + i * 256;
                int aRow = slot >> 2, aCol = (slot & 3) * 4;
                aReg[i] = loadA4(rowBlk + aRow, k0 + aCol);
                int bRow = slot >> 5, bCol = (slot & 31) * 4;
                bReg[i] = *reinterpret_cast<const float4*>(Bg + (size_t)(k0 + bRow) * N + colBlk + bCol);
            }
        }

        // compute
        #pragma unroll
        for (int k = 0; k < BK; k++) {
            const ulonglong2* ap = reinterpret_cast<const ulonglong2*>(&As2[k][tRow * 8]);
            ulonglong2 a01 = ap[0], a23 = ap[1], a45 = ap[2], a67 = ap[3];
            ull_t m2[8] = {a01.x, a01.y, a23.x, a23.y, a45.x, a45.y, a67.x, a67.y};
            const ulonglong2* bp = reinterpret_cast<const ulonglong2*>(&Bs[k][tCol * 8]);
            ulonglong2 b01 = bp[0], b23 = bp[1];
            ull_t n2[4] = {b01.x, b01.y, b23.x, b23.y};
            #pragma unroll
            for (int i = 0; i < 8; i++)
                #pragma unroll
                for (int j = 0; j < 4; j++)
                    acc[i][j] = fma2(m2[i], n2[j], acc[i][j]);
        }
        __syncthreads();
    }

    // epilogue
    const int row0 = rowBlk + tRow * 8;
    const int colb = colBlk + tCol * 8;
    float bvals[8];
    if (HASBIAS) {
        float4 b0 = *reinterpret_cast<const float4*>(bias + colb);
        float4 b1 = *reinterpret_cast<const float4*>(bias + colb + 4);
        bvals[0] = bias_scale * b0.x; bvals[1] = bias_scale * b0.y;
        bvals[2] = bias_scale * b0.z; bvals[3] = bias_scale * b0.w;
        bvals[4] = bias_scale * b1.x; bvals[5] = bias_scale * b1.y;
        bvals[6] = bias_scale * b1.z; bvals[7] = bias_scale * b1.w;
    }
    #pragma unroll
    for (int i = 0; i < 8; i++) {
        float o[8];
        #pragma unroll
        for (int j = 0; j < 4; j++) unpack2(acc[i][j], o[2 * j], o[2 * j + 1]);
        if (HASBIAS) {
            #pragma unroll
            for (int q = 0; q < 8; q++) o[q] += bvals[q];
        }
        if (SOFTPLUS) {
            #pragma unroll
            for (int q = 0; q < 8; q++) o[q] = softplus_f(o[q]);
        }
        float4 s0 = make_float4(o[0], o[1], o[2], o[3]);
        float4 s1 = make_float4(o[4], o[5], o[6], o[7]);
        float* cp = C + (size_t)(row0 + i) * N + colb;
        *reinterpret_cast<float4*>(cp)     = s0;
        *reinterpret_cast<float4*>(cp + 4) = s1;
    }
}

// ---------------------------------------------------------------------------
// Depthwise conv (k=4, SAME pad: left=1 right=2) + SiLU, over one half of xz
// ---------------------------------------------------------------------------
__global__ __launch_bounds__(256)
void conv_silu_kernel(const float* __restrict__ xz, int col0,
                      const float* __restrict__ w,     // (4,1,DHALF): w[j*DHALF+c]
                      const float* __restrict__ bias,  // (DHALF)
                      float* __restrict__ out)         // (MROWS, DHALF)
{
    int idx = blockIdx.x * blockDim.x + threadIdx.x;   // < MROWS*DHALF
    int c  = idx & (DHALF - 1);
    int bl = idx >> 10;
    int l  = bl & (LSEQ - 1);

    float acc = bias[c];
    const float* src = xz + (size_t)bl * DINNER + col0 + c;
    #pragma unroll
    for (int j = 0; j < 4; j++) {
        int ll = l + j - 1;
        if (ll >= 0 && ll < LSEQ)
            acc = fmaf(src[(ptrdiff_t)(j - 1) * DINNER], w[j * DHALF + c], acc);
    }
    out[idx] = silu_f(acc);
}

// ---------------------------------------------------------------------------
// x_dbl GEMM: C[8192,96] = xs[8192,1024] @ W_xdbl[1024,96]
//   BM=64, BK=16, 256 threads, 4x6 outputs/thread
// ---------------------------------------------------------------------------
__global__ __launch_bounds__(256)
void gemm_xdbl_kernel(const float* __restrict__ A,
                      const float* __restrict__ Bg,
                      float* __restrict__ C)
{
    constexpr int BM = 64, BK = 16;
    __shared__ float As[BK][BM + 4];
    __shared__ float Bs[BK][XDBL_N];

    const int tid    = threadIdx.x;
    const int rowBlk = blockIdx.x * BM;
    const int tRow   = tid >> 4;   // 0..15 -> 4 rows each
    const int tCol   = tid & 15;   // 0..15 -> 6 cols each

    float acc[4][6];
    #pragma unroll
    for (int i = 0; i < 4; i++)
        #pragma unroll
        for (int j = 0; j < 6; j++) acc[i][j] = 0.0f;

    const int aRow = tid >> 2;
    const int aCol = (tid & 3) << 2;

    for (int k0 = 0; k0 < DHALF; k0 += BK) {
        float4 av = *reinterpret_cast<const float4*>(
            A + (size_t)(rowBlk + aRow) * DHALF + k0 + aCol);
        As[aCol + 0][aRow] = av.x;
        As[aCol + 1][aRow] = av.y;
        As[aCol + 2][aRow] = av.z;
        As[aCol + 3][aRow] = av.w;
        #pragma unroll
        for (int i = 0; i < 6; i++) {
            int idx = tid + i * 256;          // < 1536
            int r = idx / XDBL_N, cc = idx % XDBL_N;
            Bs[r][cc] = Bg[(size_t)(k0 + r) * XDBL_N + cc];
        }
        __syncthreads();
        #pragma unroll
        for (int k = 0; k < BK; k++) {
            float a[4], bb[6];
            #pragma unroll
            for (int i = 0; i < 4; i++) a[i] = As[k][tRow * 4 + i];
            #pragma unroll
            for (int j = 0; j < 6; j++) bb[j] = Bs[k][tCol * 6 + j];
            #pragma unroll
            for (int i = 0; i < 4; i++)
                #pragma unroll
                for (int j = 0; j < 6; j++)
                    acc[i][j] = fmaf(a[i], bb[j], acc[i][j]);
        }
        __syncthreads();
    }
    #pragma unroll
    for (int i = 0; i < 4; i++)
        #pragma unroll
        for (int j = 0; j < 6; j++)
            C[(size_t)(rowBlk + tRow * 4 + i) * XDBL_N + tCol * 6 + j] = acc[i][j];
}

// ---------------------------------------------------------------------------
// Selective scan. A[d][n] = -(n+1)  =>  dA_n = exp(-delta)^(n+1) (power tree).
//   One thread per channel d; block = 128 channels of one batch; 32 blocks.
//   y[t] = sum_n h_n * C_t[n] + u*D,  h_n <- dA_n*h_n + (delta*u)*B_t[n]
// ---------------------------------------------------------------------------
__global__ __launch_bounds__(128)
void scan_kernel(const float* __restrict__ delta, const float* __restrict__ u,
                 const float* __restrict__ xdbl,  const float* __restrict__ Dv,
                 float* __restrict__ y)
{
    const int tid = threadIdx.x;
    const int b   = blockIdx.x >> 3;
    const int d   = ((blockIdx.x & 7) << 7) + tid;

    __shared__ float sB[16][DSTATE];
    __shared__ float sC[16][DSTATE];
    __shared__ float sd[16][128];
    __shared__ float su[16][128];

    float h[DSTATE];
    #pragma unroll
    for (int n = 0; n < DSTATE; n++) h[n] = 0.0f;
    const float Dd = Dv[d];
    const size_t baseRow = (size_t)b * LSEQ;

    for (int t0 = 0; t0 < LSEQ; t0 += 16) {
        // stage B/C (32 floats x 16 steps): one float4 per thread
        {
            int s = tid >> 3;
            int i = (tid & 7) << 2;
            float4 v = *reinterpret_cast<const float4*>(
                xdbl + (baseRow + t0 + s) * XDBL_N + DTRANK + i);
            float vv[4] = {v.x, v.y, v.z, v.w};
            #pragma unroll
            for (int q = 0; q < 4; q++) {
                int ii = i + q;
                if (ii < DSTATE) sB[s][ii] = vv[q];
                else             sC[s][ii - DSTATE] = vv[q];
            }
        }
        // stage delta/u (coalesced, high MLP)
        #pragma unroll
        for (int s = 0; s < 16; s++) {
            size_t r = (baseRow + t0 + s) * DHALF + d;
            sd[s][tid] = delta[r];
            su[s][tid] = u[r];
        }
        __syncthreads();

        #pragma unroll
        for (int s = 0; s < 16; s++) {
            float dl = sd[s][tid];
            float uu = su[s][tid];
            float du = dl * uu;
            float p1 = __expf(-dl);
            float p2 = p1 * p1, p3 = p2 * p1, p4 = p2 * p2;
            float p5 = p4 * p1, p6 = p4 * p2, p7 = p4 * p3, p8 = p4 * p4;
            float pw[16] = {p1, p2, p3, p4, p5, p6, p7, p8,
                            p8 * p1, p8 * p2, p8 * p3, p8 * p4,
                            p8 * p5, p8 * p6, p8 * p7, p8 * p8};
            float y0 = 0.f, y1 = 0.f, y2 = 0.f, y3 = 0.f;
            #pragma unroll
            for (int n = 0; n < DSTATE; n += 4) {
                h[n + 0] = fmaf(pw[n + 0], h[n + 0], du * sB[s][n + 0]);
                h[n + 1] = fmaf(pw[n + 1], h[n + 1], du * sB[s][n + 1]);
                h[n + 2] = fmaf(pw[n + 2], h[n + 2], du * sB[s][n + 2]);
                h[n + 3] = fmaf(pw[n + 3], h[n + 3], du * sB[s][n + 3]);
                y0 = fmaf(h[n + 0], sC[s][n + 0], y0);
                y1 = fmaf(h[n + 1], sC[s][n + 1], y1);
                y2 = fmaf(h[n + 2], sC[s][n + 2], y2);
                y3 = fmaf(h[n + 3], sC[s][n + 3], y3);
            }
            y[(baseRow + t0 + s) * DHALF + d] = fmaf(uu, Dd, (y0 + y1) + (y2 + y3));
        }
        __syncthreads();
    }
}

// ---------------------------------------------------------------------------
// Launch
// ---------------------------------------------------------------------------
extern "C" void kernel_launch(void* const* d_in, const int* in_sizes, int n_in,
                              void* d_out, int out_size)
{
    const float* x        = (const float*)d_in[0];
    const float* W_in     = (const float*)d_in[1];
    const float* conv_x_w = (const float*)d_in[2];
    const float* conv_x_b = (const float*)d_in[3];
    const float* conv_z_w = (const float*)d_in[4];
    const float* conv_z_b = (const float*)d_in[5];
    const float* W_xdbl   = (const float*)d_in[6];
    const float* W_dt     = (const float*)d_in[7];
    const float* inv_dt   = (const float*)d_in[8];
    const float* Dvec     = (const float*)d_in[9];
    const float* W_out    = (const float*)d_in[10];
    const float* b_out    = (const float*)d_in[11];
    float* out            = (float*)d_out;

    float *p_xz, *p_xs, *p_z, *p_xdbl, *p_delta, *p_y;
    cudaGetSymbolAddress((void**)&p_xz,    g_xz);
    cudaGetSymbolAddress((void**)&p_xs,    g_xs);
    cudaGetSymbolAddress((void**)&p_z,     g_z);
    cudaGetSymbolAddress((void**)&p_xdbl,  g_xdbl);
    cudaGetSymbolAddress((void**)&p_delta, g_delta);
    cudaGetSymbolAddress((void**)&p_y,     g_y);

    // 1) xz = x @ W_in                               [8192,2048]
    sgemm_f32x2_kernel<false, false>
        <<<dim3(DINNER / 128, MROWS / 128), 256>>>(
            x, DMODEL, DMODEL, x, DMODEL, W_in,
            nullptr, 0.0f, p_xz, MROWS, DINNER, DMODEL);

    // 2) depthwise conv + silu on both halves
    conv_silu_kernel<<<(MROWS * DHALF) / 256, 256>>>(p_xz, 0,     conv_x_w, conv_x_b, p_xs);
    conv_silu_kernel<<<(MROWS * DHALF) / 256, 256>>>(p_xz, DHALF, conv_z_w, conv_z_b, p_z);

    // 3) x_dbl = xs @ W_xdbl                          [8192,96]
    gemm_xdbl_kernel<<<MROWS / 64, 256>>>(p_xs, W_xdbl, p_xdbl);

    // 4) delta = softplus(dt_low @ W_dt + 2*inv_dt)   [8192,1024]
    //    (A = x_dbl[:, :64], row stride 96)
    sgemm_f32x2_kernel<true, true>
        <<<dim3(DHALF / 128, MROWS / 128), 256>>>(
            p_xdbl, XDBL_N, DTRANK, p_xdbl, XDBL_N, W_dt,
            inv_dt, 2.0f, p_delta, MROWS, DHALF, DTRANK);

    // 5) selective scan -> y (+ u*D)                  [8192,1024]
    scan_kernel<<<B_SZ * 8, 128>>>(p_delta, p_xs, p_xdbl, Dvec, p_y);

    // 6) out = [y | z] @ W_out + b_out                [8192,1024]
    sgemm_f32x2_kernel<false, true>
        <<<dim3(DMODEL / 128, MROWS / 128), 256>>>(
            p_y, DHALF, DHALF, p_z, DHALF, W_out,
            b_out, 1.0f, out, MROWS, DMODEL, DINNER);
}

// round 3
// speedup vs baseline: 2.3549x; 2.3549x over previous
#include <cuda_runtime.h>
#include <cuda_bf16.h>
#include <cstdint>
#include <cstddef>

// ---------------------------------------------------------------------------
// Problem constants (MambaVisionMixer, B=4, L=2048)
// ---------------------------------------------------------------------------
#define B_SZ    4
#define LSEQ    2048
#define DMODEL  1024
#define DINNER  2048
#define DHALF   1024
#define DSTATE  16
#define DTRANK  64
#define XDBL_N  96
#define MROWS   (B_SZ*LSEQ)   // 8192

typedef __nv_bfloat16 bf16;

// ---------------------------------------------------------------------------
// Device scratch (static __device__ arrays — no allocations)
// ---------------------------------------------------------------------------
__device__ float g_xz   [(size_t)MROWS * DINNER];   // 64 MB
__device__ float g_xs   [(size_t)MROWS * DHALF];    // 32 MB
__device__ float g_xdbl [(size_t)MROWS * XDBL_N];   // 3 MB
__device__ float g_delta[(size_t)MROWS * DHALF];    // 32 MB

__device__ bf16 g_a1h[(size_t)MROWS * DMODEL];      // x hi
__device__ bf16 g_a1l[(size_t)MROWS * DMODEL];      // x lo
__device__ bf16 g_b1h[(size_t)DINNER * DMODEL];     // W_in^T hi  [2048,1024]
__device__ bf16 g_b1l[(size_t)DINNER * DMODEL];
__device__ bf16 g_xsh[(size_t)MROWS * DHALF];       // xs hi
__device__ bf16 g_xsl[(size_t)MROWS * DHALF];
__device__ bf16 g_bxh[(size_t)XDBL_N * DHALF];      // W_xdbl^T [96,1024]
__device__ bf16 g_bxl[(size_t)XDBL_N * DHALF];
__device__ bf16 g_dth[(size_t)MROWS * DTRANK];      // dt_low hi [8192,64]
__device__ bf16 g_dtl[(size_t)MROWS * DTRANK];
__device__ bf16 g_bdh[(size_t)DHALF * DTRANK];      // W_dt^T [1024,64]
__device__ bf16 g_bdl[(size_t)DHALF * DTRANK];
__device__ bf16 g_ch [(size_t)MROWS * DINNER];      // [y|z] hi [8192,2048]
__device__ bf16 g_cl [(size_t)MROWS * DINNER];
__device__ bf16 g_b2h[(size_t)DMODEL * DINNER];     // W_out^T [1024,2048]
__device__ bf16 g_b2l[(size_t)DMODEL * DINNER];

// ---------------------------------------------------------------------------
// Helpers (sm_80-era ISA only: compiles at compute_103 non-'a' target)
// ---------------------------------------------------------------------------
__device__ __forceinline__ uint32_t smem_u32(const void* p) {
    uint32_t r;
    asm("{ .reg .u64 t; cvta.to.shared.u64 t, %1; cvt.u32.u64 %0, t; }"
        : "=r"(r) : "l"(p));
    return r;
}

#define CP16(dst, src) \
    asm volatile("cp.async.cg.shared.global [%0], [%1], 16;" \
        :: "r"(dst), "l"(src) : "memory")
#define CP16Z(dst, src, sz) \
    asm volatile("cp.async.cg.shared.global [%0], [%1], 16, %2;" \
        :: "r"(dst), "l"(src), "r"(sz) : "memory")
#define CP_COMMIT() asm volatile("cp.async.commit_group;" ::: "memory")
#define CP_WAIT2()  asm volatile("cp.async.wait_group 2;" ::: "memory")

__device__ __forceinline__ void ldsm4(uint32_t* r, uint32_t addr) {
    asm volatile("ldmatrix.sync.aligned.m8n8.x4.shared.b16 {%0,%1,%2,%3}, [%4];"
        : "=r"(r[0]), "=r"(r[1]), "=r"(r[2]), "=r"(r[3]) : "r"(addr));
}

__device__ __forceinline__ void mma16816(float* d, const uint32_t* a,
                                         const uint32_t* b) {
    asm volatile(
        "mma.sync.aligned.m16n8k16.row.col.f32.bf16.bf16.f32 "
        "{%0,%1,%2,%3}, {%4,%5,%6,%7}, {%8,%9}, {%0,%1,%2,%3};"
        : "+f"(d[0]), "+f"(d[1]), "+f"(d[2]), "+f"(d[3])
        : "r"(a[0]), "r"(a[1]), "r"(a[2]), "r"(a[3]), "r"(b[0]), "r"(b[1]));
}

__device__ __forceinline__ float softplus_f(float x) {
    return fmaxf(x, 0.0f) + log1pf(expf(-fabsf(x)));
}
__device__ __forceinline__ float silu_f(float x) {
    return x / (1.0f + expf(-x));
}
__device__ __forceinline__ void split_bf16(float v, bf16& h, bf16& l) {
    h = __float2bfloat16(v);
    l = __float2bfloat16(v - __bfloat162float(h));
}

// ---------------------------------------------------------------------------
// Tensor-core GEMM (mma.sync bf16, fp32 accum) with bf16-split emulation.
//   C[M,N] = (Ahi+Alo)[M,K] @ (Bhi+Blo)^T   (B stored [N,K] row-major)
//   3 product streams as extended K: (Ahi,Bhi), (Ahi,Blo), (Alo,Bhi).
//   CTA 128x128, 8 warps (2x4), warp tile 64x32, BK=32, 4-stage cp.async.
//   Smem rows are 64B (32 bf16); XOR swizzle c ^= (row>>1)&3 gives 8 distinct
//   16B bank-groups across any 8 consecutive rows (conflict-free ldmatrix).
// ---------------------------------------------------------------------------
template <bool SOFTPLUS, bool HASBIAS, bool NCHK>
__global__ __launch_bounds__(256, 2)
void gemm_mma(const bf16* __restrict__ Ahi, const bf16* __restrict__ Alo,
              const bf16* __restrict__ Bhi, const bf16* __restrict__ Blo,
              const float* __restrict__ bias, float bias_scale,
              float* __restrict__ C, int N, int K, int Brows)
{
    constexpr int STAGE = 16384;     // A 128x64B + B 128x64B
    extern __shared__ char dsm[];
    const uint32_t base = (smem_u32(dsm) + 1023u) & ~1023u;

    const int tid    = threadIdx.x;
    const int rowBlk = blockIdx.y * 128;
    const int colBlk = blockIdx.x * 128;
    const int wid    = tid >> 5;
    const int lane   = tid & 31;
    const int warp_m = wid >> 2;          // 0..1 -> 64 rows
    const int warp_n = wid & 3;           // 0..3 -> 32 cols
    const int mat    = lane >> 3;
    const int rin    = lane & 7;

    const int KC     = K / 32;
    const int CHUNKS = 3 * KC;

    // --- precomputed ldmatrix offsets (relative to stage base) ---
    uint32_t offA[4][2], offB[2][2];
    #pragma unroll
    for (int mi = 0; mi < 4; mi++)
        #pragma unroll
        for (int j = 0; j < 2; j++) {
            int row = warp_m * 64 + mi * 16 + (mat & 1) * 8 + rin;
            int c   = 2 * j + (mat >> 1);
            offA[mi][j] = row * 64 + ((c ^ ((row >> 1) & 3)) << 4);
        }
    #pragma unroll
    for (int bi = 0; bi < 2; bi++)
        #pragma unroll
        for (int j = 0; j < 2; j++) {
            int row = warp_n * 32 + bi * 16 + (mat >> 1) * 8 + rin;
            int c   = 2 * j + (mat & 1);
            offB[bi][j] = 8192 + row * 64 + ((c ^ ((row >> 1) & 3)) << 4);
        }

    float acc[4][4][4];
    #pragma unroll
    for (int i = 0; i < 4; i++)
        #pragma unroll
        for (int j = 0; j < 4; j++)
            #pragma unroll
            for (int q = 0; q < 4; q++) acc[i][j][q] = 0.0f;

    auto load_stage = [&](int s, int c) {
        int stream = (c >= 2 * KC) ? 2 : ((c >= KC) ? 1 : 0);
        int k0 = (c - stream * KC) * 32;
        const bf16* Ap = (stream == 2) ? Alo : Ahi;
        const bf16* Bp = (stream == 1) ? Blo : Bhi;
        uint32_t as_ = base + s * STAGE;
        uint32_t bs_ = as_ + 8192;
        #pragma unroll
        for (int t = 0; t < 2; t++) {
            int idx = tid + t * 256;
            int r = idx >> 2, cc = idx & 3;
            uint32_t dst = as_ + r * 64 + ((cc ^ ((r >> 1) & 3)) << 4);
            const char* src =
                (const char*)(Ap + (size_t)(rowBlk + r) * K + k0) + cc * 16;
            CP16(dst, src);
        }
        #pragma unroll
        for (int t = 0; t < 2; t++) {
            int idx = tid + t * 256;
            int r = idx >> 2, cc = idx & 3;
            uint32_t dst = bs_ + r * 64 + ((cc ^ ((r >> 1) & 3)) << 4);
            if (NCHK) {
                int br = colBlk + r;
                int ok = (br < Brows);
                const char* src =
                    (const char*)(Bp + (size_t)(ok ? br : 0) * K + k0) + cc * 16;
                CP16Z(dst, src, ok ? 16u : 0u);
            } else {
                const char* src =
                    (const char*)(Bp + (size_t)(colBlk + r) * K + k0) + cc * 16;
                CP16(dst, src);
            }
        }
    };

    // prologue: 3 stages in flight
    #pragma unroll
    for (int s = 0; s < 3; s++) { load_stage(s, s); CP_COMMIT(); }

    for (int i = 0; i < CHUNKS; i++) {
        CP_WAIT2();              // chunk i landed
        __syncthreads();         // all warps done with chunk i-1's stage
        if (i + 3 < CHUNKS) load_stage((i + 3) & 3, i + 3);
        CP_COMMIT();

        const uint32_t sb = base + (i & 3) * STAGE;
        #pragma unroll
        for (int j = 0; j < 2; j++) {
            uint32_t Af[4][4];
            #pragma unroll
            for (int mi = 0; mi < 4; mi++) ldsm4(Af[mi], sb + offA[mi][j]);
            uint32_t Bf[4][2];
            #pragma unroll
            for (int bi = 0; bi < 2; bi++) {
                uint32_t r[4];
                ldsm4(r, sb + offB[bi][j]);
                Bf[bi * 2 + 0][0] = r[0]; Bf[bi * 2 + 0][1] = r[1];
                Bf[bi * 2 + 1][0] = r[2]; Bf[bi * 2 + 1][1] = r[3];
            }
            #pragma unroll
            for (int mi = 0; mi < 4; mi++)
                #pragma unroll
                for (int ni = 0; ni < 4; ni++)
                    mma16816(acc[mi][ni], Af[mi], Bf[ni]);
        }
    }

    // epilogue
    const int mrow = rowBlk + warp_m * 64 + (lane >> 2);
    const int ncol = colBlk + warp_n * 32 + (lane & 3) * 2;
    #pragma unroll
    for (int mi = 0; mi < 4; mi++) {
        #pragma unroll
        for (int ni = 0; ni < 4; ni++) {
            int n0 = ncol + ni * 8;
            if (NCHK && n0 >= Brows) continue;
            float v0 = acc[mi][ni][0], v1 = acc[mi][ni][1];
            float v2 = acc[mi][ni][2], v3 = acc[mi][ni][3];
            if (HASBIAS) {
                float b0 = bias_scale * __ldg(bias + n0);
                float b1 = bias_scale * __ldg(bias + n0 + 1);
                v0 += b0; v1 += b1; v2 += b0; v3 += b1;
            }
            if (SOFTPLUS) {
                v0 = softplus_f(v0); v1 = softplus_f(v1);
                v2 = softplus_f(v2); v3 = softplus_f(v3);
            }
            size_t r0 = (size_t)(mrow + mi * 16) * N + n0;
            size_t r1 = (size_t)(mrow + mi * 16 + 8) * N + n0;
            *reinterpret_cast<float2*>(C + r0) = make_float2(v0, v1);
            *reinterpret_cast<float2*>(C + r1) = make_float2(v2, v3);
        }
    }
}

// ---------------------------------------------------------------------------
// fp32 -> bf16 hi/lo split (contiguous)
// ---------------------------------------------------------------------------
__global__ __launch_bounds__(256)
void split_kernel(const float* __restrict__ in, bf16* __restrict__ oh,
                  bf16* __restrict__ ol, int n)
{
    int i = (blockIdx.x * blockDim.x + threadIdx.x) * 4;
    if (i >= n) return;
    float4 v = *reinterpret_cast<const float4*>(in + i);
    bf16 h0, l0, h1, l1, h2, l2, h3, l3;
    split_bf16(v.x, h0, l0); split_bf16(v.y, h1, l1);
    split_bf16(v.z, h2, l2); split_bf16(v.w, h3, l3);
    __nv_bfloat162* ph = reinterpret_cast<__nv_bfloat162*>(oh + i);
    __nv_bfloat162* pl = reinterpret_cast<__nv_bfloat162*>(ol + i);
    ph[0] = __nv_bfloat162(h0, h1); ph[1] = __nv_bfloat162(h2, h3);
    pl[0] = __nv_bfloat162(l0, l1); pl[1] = __nv_bfloat162(l2, l3);
}

// transpose + split:  in [R,C] fp32 -> out [C,R] bf16 hi/lo
__global__ __launch_bounds__(256)
void tsplit_kernel(const float* __restrict__ in, bf16* __restrict__ oh,
                   bf16* __restrict__ ol, int R, int C)
{
    __shared__ float t[32][33];
    const int cx = blockIdx.x * 32, ry = blockIdx.y * 32;
    const int tx = threadIdx.x, ty = threadIdx.y;   // 32 x 8
    #pragma unroll
    for (int j = ty; j < 32; j += 8)
        t[j][tx] = in[(size_t)(ry + j) * C + cx + tx];
    __syncthreads();
    #pragma unroll
    for (int j = ty; j < 32; j += 8) {
        float v = t[tx][j];
        bf16 h, l; split_bf16(v, h, l);
        size_t o = (size_t)(cx + j) * R + ry + tx;
        oh[o] = h; ol[o] = l;
    }
}

// dt_low extract+split: xdbl[:, 0:64] -> dth/dtl [MROWS,64]
__global__ __launch_bounds__(256)
void split_dt_kernel(const float* __restrict__ xdbl, bf16* __restrict__ oh,
                     bf16* __restrict__ ol)
{
    int idx = blockIdx.x * blockDim.x + threadIdx.x;   // < MROWS*64
    int c = idx & 63, r = idx >> 6;
    float v = xdbl[(size_t)r * XDBL_N + c];
    bf16 h, l; split_bf16(v, h, l);
    oh[idx] = h; ol[idx] = l;
}

// ---------------------------------------------------------------------------
// Depthwise conv (k=4, SAME: pad left 1, right 2) + SiLU
// ---------------------------------------------------------------------------
__global__ __launch_bounds__(256)
void conv_x_kernel(const float* __restrict__ xz,
                   const float* __restrict__ w, const float* __restrict__ bias,
                   float* __restrict__ out)
{
    int idx = blockIdx.x * blockDim.x + threadIdx.x;
    int c = idx & (DHALF - 1);
    int bl = idx >> 10;
    int l = bl & (LSEQ - 1);
    float acc = bias[c];
    const float* src = xz + (size_t)bl * DINNER + c;
    #pragma unroll
    for (int j = 0; j < 4; j++) {
        int ll = l + j - 1;
        if (ll >= 0 && ll < LSEQ)
            acc = fmaf(src[(ptrdiff_t)(j - 1) * DINNER], w[j * DHALF + c], acc);
    }
    out[idx] = silu_f(acc);
}

// z-half: conv + silu, write split bf16 directly into concat right half
__global__ __launch_bounds__(256)
void conv_z_kernel(const float* __restrict__ xz,
                   const float* __restrict__ w, const float* __restrict__ bias,
                   bf16* __restrict__ cat_h, bf16* __restrict__ cat_l)
{
    int idx = blockIdx.x * blockDim.x + threadIdx.x;
    int c = idx & (DHALF - 1);
    int bl = idx >> 10;
    int l = bl & (LSEQ - 1);
    float acc = bias[c];
    const float* src = xz + (size_t)bl * DINNER + DHALF + c;
    #pragma unroll
    for (int j = 0; j < 4; j++) {
        int ll = l + j - 1;
        if (ll >= 0 && ll < LSEQ)
            acc = fmaf(src[(ptrdiff_t)(j - 1) * DINNER], w[j * DHALF + c], acc);
    }
    float v = silu_f(acc);
    bf16 h, lo; split_bf16(v, h, lo);
    size_t o = (size_t)bl * DINNER + DHALF + c;
    cat_h[o] = h; cat_l[o] = lo;
}

// ---------------------------------------------------------------------------
// Selective scan.  A[d][n] = -(n+1) => dA_n = exp(-delta)^(n+1) (power tree)
// Output written as split bf16 into concat left half.
// ---------------------------------------------------------------------------
__global__ __launch_bounds__(128)
void scan_kernel(const float* __restrict__ delta, const float* __restrict__ u,
                 const float* __restrict__ xdbl, const float* __restrict__ Dv,
                 bf16* __restrict__ cat_h, bf16* __restrict__ cat_l)
{
    const int tid = threadIdx.x;
    const int b = blockIdx.x >> 3;
    const int d = ((blockIdx.x & 7) << 7) + tid;

    __shared__ float sB[16][DSTATE];
    __shared__ float sC[16][DSTATE];
    __shared__ float sd[16][128];
    __shared__ float su[16][128];

    float h[DSTATE];
    #pragma unroll
    for (int n = 0; n < DSTATE; n++) h[n] = 0.0f;
    const float Dd = Dv[d];
    const size_t baseRow = (size_t)b * LSEQ;

    for (int t0 = 0; t0 < LSEQ; t0 += 16) {
        {
            int s = tid >> 3;
            int i = (tid & 7) << 2;
            float4 v = *reinterpret_cast<const float4*>(
                xdbl + (baseRow + t0 + s) * XDBL_N + DTRANK + i);
            float vv[4] = {v.x, v.y, v.z, v.w};
            #pragma unroll
            for (int q = 0; q < 4; q++) {
                int ii = i + q;
                if (ii < DSTATE) sB[s][ii] = vv[q];
                else             sC[s][ii - DSTATE] = vv[q];
            }
        }
        #pragma unroll
        for (int s = 0; s < 16; s++) {
            size_t r = (baseRow + t0 + s) * DHALF + d;
            sd[s][tid] = delta[r];
            su[s][tid] = u[r];
        }
        __syncthreads();

        #pragma unroll
        for (int s = 0; s < 16; s++) {
            float dl = sd[s][tid];
            float uu = su[s][tid];
            float du = dl * uu;
            float p1 = __expf(-dl);
            float p2 = p1 * p1, p3 = p2 * p1, p4 = p2 * p2;
            float p5 = p4 * p1, p6 = p4 * p2, p7 = p4 * p3, p8 = p4 * p4;
            float pw[16] = {p1, p2, p3, p4, p5, p6, p7, p8,
                            p8 * p1, p8 * p2, p8 * p3, p8 * p4,
                            p8 * p5, p8 * p6, p8 * p7, p8 * p8};
            float y0 = 0.f, y1 = 0.f, y2 = 0.f, y3 = 0.f;
            #pragma unroll
            for (int n = 0; n < DSTATE; n += 4) {
                h[n + 0] = fmaf(pw[n + 0], h[n + 0], du * sB[s][n + 0]);
                h[n + 1] = fmaf(pw[n + 1], h[n + 1], du * sB[s][n + 1]);
                h[n + 2] = fmaf(pw[n + 2], h[n + 2], du * sB[s][n + 2]);
                h[n + 3] = fmaf(pw[n + 3], h[n + 3], du * sB[s][n + 3]);
                y0 = fmaf(h[n + 0], sC[s][n + 0], y0);
                y1 = fmaf(h[n + 1], sC[s][n + 1], y1);
                y2 = fmaf(h[n + 2], sC[s][n + 2], y2);
                y3 = fmaf(h[n + 3], sC[s][n + 3], y3);
            }
            float yv = fmaf(uu, Dd, (y0 + y1) + (y2 + y3));
            bf16 hh, ll; split_bf16(yv, hh, ll);
            size_t o = (baseRow + t0 + s) * DINNER + d;
            cat_h[o] = hh; cat_l[o] = ll;
        }
        __syncthreads();
    }
}

// ---------------------------------------------------------------------------
// Launch
// ---------------------------------------------------------------------------
extern "C" void kernel_launch(void* const* d_in, const int* in_sizes, int n_in,
                              void* d_out, int out_size)
{
    const float* x        = (const float*)d_in[0];
    const float* W_in     = (const float*)d_in[1];
    const float* conv_x_w = (const float*)d_in[2];
    const float* conv_x_b = (const float*)d_in[3];
    const float* conv_z_w = (const float*)d_in[4];
    const float* conv_z_b = (const float*)d_in[5];
    const float* W_xdbl   = (const float*)d_in[6];
    const float* W_dt     = (const float*)d_in[7];
    const float* inv_dt   = (const float*)d_in[8];
    const float* Dvec     = (const float*)d_in[9];
    const float* W_out    = (const float*)d_in[10];
    const float* b_out    = (const float*)d_in[11];
    float* out            = (float*)d_out;

    float *p_xz, *p_xs, *p_xdbl, *p_delta;
    bf16 *p_a1h, *p_a1l, *p_b1h, *p_b1l, *p_xsh, *p_xsl, *p_bxh, *p_bxl;
    bf16 *p_dth, *p_dtl, *p_bdh, *p_bdl, *p_ch, *p_cl, *p_b2h, *p_b2l;
    cudaGetSymbolAddress((void**)&p_xz,    g_xz);
    cudaGetSymbolAddress((void**)&p_xs,    g_xs);
    cudaGetSymbolAddress((void**)&p_xdbl,  g_xdbl);
    cudaGetSymbolAddress((void**)&p_delta, g_delta);
    cudaGetSymbolAddress((void**)&p_a1h, g_a1h); cudaGetSymbolAddress((void**)&p_a1l, g_a1l);
    cudaGetSymbolAddress((void**)&p_b1h, g_b1h); cudaGetSymbolAddress((void**)&p_b1l, g_b1l);
    cudaGetSymbolAddress((void**)&p_xsh, g_xsh); cudaGetSymbolAddress((void**)&p_xsl, g_xsl);
    cudaGetSymbolAddress((void**)&p_bxh, g_bxh); cudaGetSymbolAddress((void**)&p_bxl, g_bxl);
    cudaGetSymbolAddress((void**)&p_dth, g_dth); cudaGetSymbolAddress((void**)&p_dtl, g_dtl);
    cudaGetSymbolAddress((void**)&p_bdh, g_bdh); cudaGetSymbolAddress((void**)&p_bdl, g_bdl);
    cudaGetSymbolAddress((void**)&p_ch,  g_ch);  cudaGetSymbolAddress((void**)&p_cl,  g_cl);
    cudaGetSymbolAddress((void**)&p_b2h, g_b2h); cudaGetSymbolAddress((void**)&p_b2l, g_b2l);

    constexpr int SMEM = 4 * 16384 + 1024;   // 66560
    cudaFuncSetAttribute(gemm_mma<false,false,false>,
                         cudaFuncAttributeMaxDynamicSharedMemorySize, SMEM);
    cudaFuncSetAttribute(gemm_mma<false,false,true>,
                         cudaFuncAttributeMaxDynamicSharedMemorySize, SMEM);
    cudaFuncSetAttribute(gemm_mma<true,true,false>,
                         cudaFuncAttributeMaxDynamicSharedMemorySize, SMEM);
    cudaFuncSetAttribute(gemm_mma<false,true,false>,
                         cudaFuncAttributeMaxDynamicSharedMemorySize, SMEM);

    // 1) weight transposes + splits
    tsplit_kernel<<<dim3(DINNER / 32, DMODEL / 32), dim3(32, 8)>>>(W_in,   p_b1h, p_b1l, DMODEL, DINNER);
    tsplit_kernel<<<dim3(XDBL_N / 32, DHALF / 32),  dim3(32, 8)>>>(W_xdbl, p_bxh, p_bxl, DHALF,  XDBL_N);
    tsplit_kernel<<<dim3(DHALF / 32, DTRANK / 32),  dim3(32, 8)>>>(W_dt,   p_bdh, p_bdl, DTRANK, DHALF);
    tsplit_kernel<<<dim3(DMODEL / 32, DINNER / 32), dim3(32, 8)>>>(W_out,  p_b2h, p_b2l, DINNER, DMODEL);

    // 2) split x
    split_kernel<<<(MROWS * DMODEL / 4) / 256, 256>>>(x, p_a1h, p_a1l, MROWS * DMODEL);

    // 3) xz = x @ W_in                              [8192,2048]
    gemm_mma<false,false,false><<<dim3(DINNER / 128, MROWS / 128), 256, SMEM>>>(
        p_a1h, p_a1l, p_b1h, p_b1l, nullptr, 0.0f, p_xz, DINNER, DMODEL, DINNER);

    // 4) depthwise convs + silu
    conv_x_kernel<<<(MROWS * DHALF) / 256, 256>>>(p_xz, conv_x_w, conv_x_b, p_xs);
    conv_z_kernel<<<(MROWS * DHALF) / 256, 256>>>(p_xz, conv_z_w, conv_z_b, p_ch, p_cl);

    // 5) split xs
    split_kernel<<<(MROWS * DHALF / 4) / 256, 256>>>(p_xs, p_xsh, p_xsl, MROWS * DHALF);

    // 6) x_dbl = xs @ W_xdbl                        [8192,96] (B rows zfilled to 128)
    gemm_mma<false,false,true><<<dim3(1, MROWS / 128), 256, SMEM>>>(
        p_xsh, p_xsl, p_bxh, p_bxl, nullptr, 0.0f, p_xdbl, XDBL_N, DHALF, XDBL_N);

    // 7) dt_low extract + split
    split_dt_kernel<<<(MROWS * DTRANK) / 256, 256>>>(p_xdbl, p_dth, p_dtl);

    // 8) delta = softplus(dt_low @ W_dt + 2*inv_dt) [8192,1024]
    gemm_mma<true,true,false><<<dim3(DHALF / 128, MROWS / 128), 256, SMEM>>>(
        p_dth, p_dtl, p_bdh, p_bdl, inv_dt, 2.0f, p_delta, DHALF, DTRANK, DHALF);

    // 9) selective scan -> concat left half (split bf16)
    scan_kernel<<<B_SZ * 8, 128>>>(p_delta, p_xs, p_xdbl, Dvec, p_ch, p_cl);

    // 10) out = [y|z] @ W_out + b_out               [8192,1024]
    gemm_mma<false,true,false><<<dim3(DMODEL / 128, MROWS / 128), 256, SMEM>>>(
        p_ch, p_cl, p_b2h, p_b2l, b_out, 1.0f, out, DMODEL, DINNER, DMODEL);
}

// round 4
// speedup vs baseline: 3.1564x; 1.3403x over previous
#include <cuda_runtime.h>
#include <cuda_bf16.h>
#include <cstdint>
#include <cstddef>

// ---------------------------------------------------------------------------
// Problem constants (MambaVisionMixer, B=4, L=2048)
// ---------------------------------------------------------------------------
#define B_SZ    4
#define LSEQ    2048
#define DMODEL  1024
#define DINNER  2048
#define DHALF   1024
#define DSTATE  16
#define DTRANK  64
#define XDBL_N  96
#define MROWS   (B_SZ*LSEQ)   // 8192
#define NCHUNK  16
#define LCHUNK  (LSEQ/NCHUNK) // 128

typedef __nv_bfloat16 bf16;

// ---------------------------------------------------------------------------
// Device scratch (static __device__ arrays — no allocations)
// ---------------------------------------------------------------------------
__device__ float g_xz   [(size_t)MROWS * DINNER];   // 64 MB
__device__ float g_xs   [(size_t)MROWS * DHALF];    // 32 MB
__device__ float g_xdbl [(size_t)MROWS * XDBL_N];   // 3 MB
__device__ float g_delta[(size_t)MROWS * DHALF];    // 32 MB

__device__ float g_q [(size_t)B_SZ * NCHUNK * DSTATE * DHALF];  // 4 MB
__device__ float g_hs[(size_t)B_SZ * NCHUNK * DSTATE * DHALF];  // 4 MB
__device__ float g_S [(size_t)B_SZ * NCHUNK * DHALF];           // 256 KB

__device__ bf16 g_a1h[(size_t)MROWS * DMODEL];      // x hi
__device__ bf16 g_a1l[(size_t)MROWS * DMODEL];      // x lo
__device__ bf16 g_b1h[(size_t)DINNER * DMODEL];     // W_in^T hi  [2048,1024]
__device__ bf16 g_b1l[(size_t)DINNER * DMODEL];
__device__ bf16 g_xsh[(size_t)MROWS * DHALF];       // xs hi
__device__ bf16 g_xsl[(size_t)MROWS * DHALF];
__device__ bf16 g_bxh[(size_t)XDBL_N * DHALF];      // W_xdbl^T [96,1024]
__device__ bf16 g_bxl[(size_t)XDBL_N * DHALF];
__device__ bf16 g_dth[(size_t)MROWS * DTRANK];      // dt_low hi [8192,64]
__device__ bf16 g_dtl[(size_t)MROWS * DTRANK];
__device__ bf16 g_bdh[(size_t)DHALF * DTRANK];      // W_dt^T [1024,64]
__device__ bf16 g_bdl[(size_t)DHALF * DTRANK];
__device__ bf16 g_ch [(size_t)MROWS * DINNER];      // [y|z] hi [8192,2048]
__device__ bf16 g_cl [(size_t)MROWS * DINNER];
__device__ bf16 g_b2h[(size_t)DMODEL * DINNER];     // W_out^T [1024,2048]
__device__ bf16 g_b2l[(size_t)DMODEL * DINNER];

// ---------------------------------------------------------------------------
// Helpers (sm_80-era ISA only: compiles at compute_103 non-'a' target)
// ---------------------------------------------------------------------------
__device__ __forceinline__ uint32_t smem_u32(const void* p) {
    uint32_t r;
    asm("{ .reg .u64 t; cvta.to.shared.u64 t, %1; cvt.u32.u64 %0, t; }"
        : "=r"(r) : "l"(p));
    return r;
}

#define CP16(dst, src) \
    asm volatile("cp.async.cg.shared.global [%0], [%1], 16;" \
        :: "r"(dst), "l"(src) : "memory")
#define CP16Z(dst, src, sz) \
    asm volatile("cp.async.cg.shared.global [%0], [%1], 16, %2;" \
        :: "r"(dst), "l"(src), "r"(sz) : "memory")
#define CP_COMMIT() asm volatile("cp.async.commit_group;" ::: "memory")
#define CP_WAIT2()  asm volatile("cp.async.wait_group 2;" ::: "memory")

__device__ __forceinline__ void ldsm4(uint32_t* r, uint32_t addr) {
    asm volatile("ldmatrix.sync.aligned.m8n8.x4.shared.b16 {%0,%1,%2,%3}, [%4];"
        : "=r"(r[0]), "=r"(r[1]), "=r"(r[2]), "=r"(r[3]) : "r"(addr));
}

__device__ __forceinline__ void mma16816(float* d, const uint32_t* a,
                                         const uint32_t* b) {
    asm volatile(
        "mma.sync.aligned.m16n8k16.row.col.f32.bf16.bf16.f32 "
        "{%0,%1,%2,%3}, {%4,%5,%6,%7}, {%8,%9}, {%0,%1,%2,%3};"
        : "+f"(d[0]), "+f"(d[1]), "+f"(d[2]), "+f"(d[3])
        : "r"(a[0]), "r"(a[1]), "r"(a[2]), "r"(a[3]), "r"(b[0]), "r"(b[1]));
}

__device__ __forceinline__ float softplus_f(float x) {
    return fmaxf(x, 0.0f) + log1pf(expf(-fabsf(x)));
}
__device__ __forceinline__ float silu_f(float x) {
    return x / (1.0f + expf(-x));
}
__device__ __forceinline__ void split_bf16(float v, bf16& h, bf16& l) {
    h = __float2bfloat16(v);
    l = __float2bfloat16(v - __bfloat162float(h));
}

// ---------------------------------------------------------------------------
// Tensor-core GEMM (mma.sync bf16, fp32 accum) with bf16-split emulation.
//   C[M,N] = (Ahi+Alo)[M,K] @ (Bhi+Blo)^T   (B stored [N,K] row-major)
//   3 product streams as extended K: (Ahi,Bhi), (Ahi,Blo), (Alo,Bhi).
//   CTA BMx128, 8 warps (2x4), warp tile (BM/2)x32, BK=32, 4-stage cp.async.
//   Smem rows 64B; XOR swizzle c ^= (row>>1)&3 -> conflict-free ldmatrix.
//   DTSPLIT: additionally write bf16 hi/lo of cols [0,64) to dth/dtl.
// ---------------------------------------------------------------------------
template <int BM, bool SOFTPLUS, bool HASBIAS, bool NCHK, bool DTSPLIT>
__global__ __launch_bounds__(256, 2)
void gemm_mma(const bf16* __restrict__ Ahi, const bf16* __restrict__ Alo,
              const bf16* __restrict__ Bhi, const bf16* __restrict__ Blo,
              const float* __restrict__ bias, float bias_scale,
              float* __restrict__ C, int N, int K, int Brows,
              bf16* __restrict__ dth, bf16* __restrict__ dtl)
{
    constexpr int MI    = BM / 32;          // m-iterations per warp
    constexpr int ABYTES = BM * 64;
    constexpr int STAGE = ABYTES + 8192;
    extern __shared__ char dsm[];
    const uint32_t base = (smem_u32(dsm) + 1023u) & ~1023u;

    const int tid    = threadIdx.x;
    const int rowBlk = blockIdx.y * BM;
    const int colBlk = blockIdx.x * 128;
    const int wid    = tid >> 5;
    const int lane   = tid & 31;
    const int warp_m = wid >> 2;          // 0..1 -> BM/2 rows
    const int warp_n = wid & 3;           // 0..3 -> 32 cols
    const int mat    = lane >> 3;
    const int rin    = lane & 7;

    const int KC     = K / 32;
    const int CHUNKS = 3 * KC;

    uint32_t offA[MI][2], offB[2][2];
    #pragma unroll
    for (int mi = 0; mi < MI; mi++)
        #pragma unroll
        for (int j = 0; j < 2; j++) {
            int row = warp_m * (BM / 2) + mi * 16 + (mat & 1) * 8 + rin;
            int c   = 2 * j + (mat >> 1);
            offA[mi][j] = row * 64 + ((c ^ ((row >> 1) & 3)) << 4);
        }
    #pragma unroll
    for (int bi = 0; bi < 2; bi++)
        #pragma unroll
        for (int j = 0; j < 2; j++) {
            int row = warp_n * 32 + bi * 16 + (mat >> 1) * 8 + rin;
            int c   = 2 * j + (mat & 1);
            offB[bi][j] = ABYTES + row * 64 + ((c ^ ((row >> 1) & 3)) << 4);
        }

    float acc[MI][4][4];
    #pragma unroll
    for (int i = 0; i < MI; i++)
        #pragma unroll
        for (int j = 0; j < 4; j++)
            #pragma unroll
            for (int q = 0; q < 4; q++) acc[i][j][q] = 0.0f;

    auto load_stage = [&](int s, int c) {
        int stream = (c >= 2 * KC) ? 2 : ((c >= KC) ? 1 : 0);
        int k0 = (c - stream * KC) * 32;
        const bf16* Ap = (stream == 2) ? Alo : Ahi;
        const bf16* Bp = (stream == 1) ? Blo : Bhi;
        uint32_t as_ = base + s * STAGE;
        uint32_t bs_ = as_ + ABYTES;
        #pragma unroll
        for (int t = 0; t < BM / 64; t++) {
            int idx = tid + t * 256;
            int r = idx >> 2, cc = idx & 3;
            uint32_t dst = as_ + r * 64 + ((cc ^ ((r >> 1) & 3)) << 4);
            const char* src =
                (const char*)(Ap + (size_t)(rowBlk + r) * K + k0) + cc * 16;
            CP16(dst, src);
        }
        #pragma unroll
        for (int t = 0; t < 2; t++) {
            int idx = tid + t * 256;
            int r = idx >> 2, cc = idx & 3;
            uint32_t dst = bs_ + r * 64 + ((cc ^ ((r >> 1) & 3)) << 4);
            if (NCHK) {
                int br = colBlk + r;
                int ok = (br < Brows);
                const char* src =
                    (const char*)(Bp + (size_t)(ok ? br : 0) * K + k0) + cc * 16;
                CP16Z(dst, src, ok ? 16u : 0u);
            } else {
                const char* src =
                    (const char*)(Bp + (size_t)(colBlk + r) * K + k0) + cc * 16;
                CP16(dst, src);
            }
        }
    };

    #pragma unroll
    for (int s = 0; s < 3; s++) { load_stage(s, s); CP_COMMIT(); }

    for (int i = 0; i < CHUNKS; i++) {
        CP_WAIT2();
        __syncthreads();
        if (i + 3 < CHUNKS) load_stage((i + 3) & 3, i + 3);
        CP_COMMIT();

        const uint32_t sb = base + (i & 3) * STAGE;
        #pragma unroll
        for (int j = 0; j < 2; j++) {
            uint32_t Af[MI][4];
            #pragma unroll
            for (int mi = 0; mi < MI; mi++) ldsm4(Af[mi], sb + offA[mi][j]);
            uint32_t Bf[4][2];
            #pragma unroll
            for (int bi = 0; bi < 2; bi++) {
                uint32_t r[4];
                ldsm4(r, sb + offB[bi][j]);
                Bf[bi * 2 + 0][0] = r[0]; Bf[bi * 2 + 0][1] = r[1];
                Bf[bi * 2 + 1][0] = r[2]; Bf[bi * 2 + 1][1] = r[3];
            }
            #pragma unroll
            for (int mi = 0; mi < MI; mi++)
                #pragma unroll
                for (int ni = 0; ni < 4; ni++)
                    mma16816(acc[mi][ni], Af[mi], Bf[ni]);
        }
    }

    // epilogue
    const int mrow = rowBlk + warp_m * (BM / 2) + (lane >> 2);
    const int ncol = colBlk + warp_n * 32 + (lane & 3) * 2;
    #pragma unroll
    for (int mi = 0; mi < MI; mi++) {
        #pragma unroll
        for (int ni = 0; ni < 4; ni++) {
            int n0 = ncol + ni * 8;
            if (NCHK && n0 >= Brows) continue;
            float v0 = acc[mi][ni][0], v1 = acc[mi][ni][1];
            float v2 = acc[mi][ni][2], v3 = acc[mi][ni][3];
            if (HASBIAS) {
                float b0 = bias_scale * __ldg(bias + n0);
                float b1 = bias_scale * __ldg(bias + n0 + 1);
                v0 += b0; v1 += b1; v2 += b0; v3 += b1;
            }
            if (SOFTPLUS) {
                v0 = softplus_f(v0); v1 = softplus_f(v1);
                v2 = softplus_f(v2); v3 = softplus_f(v3);
            }
            size_t r0 = (size_t)(mrow + mi * 16) * N + n0;
            size_t r1 = (size_t)(mrow + mi * 16 + 8) * N + n0;
            *reinterpret_cast<float2*>(C + r0) = make_float2(v0, v1);
            *reinterpret_cast<float2*>(C + r1) = make_float2(v2, v3);
            if (DTSPLIT && n0 < DTRANK) {
                bf16 hh, ll;
                size_t d0 = (size_t)(mrow + mi * 16) * DTRANK + n0;
                size_t d1 = (size_t)(mrow + mi * 16 + 8) * DTRANK + n0;
                split_bf16(v0, hh, ll); dth[d0] = hh;     dtl[d0] = ll;
                split_bf16(v1, hh, ll); dth[d0 + 1] = hh; dtl[d0 + 1] = ll;
                split_bf16(v2, hh, ll); dth[d1] = hh;     dtl[d1] = ll;
                split_bf16(v3, hh, ll); dth[d1 + 1] = hh; dtl[d1 + 1] = ll;
            }
        }
    }
}

// ---------------------------------------------------------------------------
// fp32 -> bf16 hi/lo split (contiguous)
// ---------------------------------------------------------------------------
__global__ __launch_bounds__(256)
void split_kernel(const float* __restrict__ in, bf16* __restrict__ oh,
                  bf16* __restrict__ ol, int n)
{
    int i = (blockIdx.x * blockDim.x + threadIdx.x) * 4;
    if (i >= n) return;
    float4 v = *reinterpret_cast<const float4*>(in + i);
    bf16 h0, l0, h1, l1, h2, l2, h3, l3;
    split_bf16(v.x, h0, l0); split_bf16(v.y, h1, l1);
    split_bf16(v.z, h2, l2); split_bf16(v.w, h3, l3);
    __nv_bfloat162* ph = reinterpret_cast<__nv_bfloat162*>(oh + i);
    __nv_bfloat162* pl = reinterpret_cast<__nv_bfloat162*>(ol + i);
    ph[0] = __nv_bfloat162(h0, h1); ph[1] = __nv_bfloat162(h2, h3);
    pl[0] = __nv_bfloat162(l0, l1); pl[1] = __nv_bfloat162(l2, l3);
}

// transpose + split:  in [R,C] fp32 -> out [C,R] bf16 hi/lo
__global__ __launch_bounds__(256)
void tsplit_kernel(const float* __restrict__ in, bf16* __restrict__ oh,
                   bf16* __restrict__ ol, int R, int C)
{
    __shared__ float t[32][33];
    const int cx = blockIdx.x * 32, ry = blockIdx.y * 32;
    const int tx = threadIdx.x, ty = threadIdx.y;   // 32 x 8
    #pragma unroll
    for (int j = ty; j < 32; j += 8)
        t[j][tx] = in[(size_t)(ry + j) * C + cx + tx];
    __syncthreads();
    #pragma unroll
    for (int j = ty; j < 32; j += 8) {
        float v = t[tx][j];
        bf16 h, l; split_bf16(v, h, l);
        size_t o = (size_t)(cx + j) * R + ry + tx;
        oh[o] = h; ol[o] = l;
    }
}

// ---------------------------------------------------------------------------
// Depthwise conv (k=4, SAME: pad left 1, right 2) + SiLU
// x-half: writes fp32 (scan input) AND split bf16 (xdbl GEMM input)
// ---------------------------------------------------------------------------
__global__ __launch_bounds__(256)
void conv_x_kernel(const float* __restrict__ xz,
                   const float* __restrict__ w, const float* __restrict__ bias,
                   float* __restrict__ out,
                   bf16* __restrict__ oh, bf16* __restrict__ ol)
{
    int idx = blockIdx.x * blockDim.x + threadIdx.x;
    int c = idx & (DHALF - 1);
    int bl = idx >> 10;
    int l = bl & (LSEQ - 1);
    float acc = bias[c];
    const float* src = xz + (size_t)bl * DINNER + c;
    #pragma unroll
    for (int j = 0; j < 4; j++) {
        int ll = l + j - 1;
        if (ll >= 0 && ll < LSEQ)
            acc = fmaf(src[(ptrdiff_t)(j - 1) * DINNER], w[j * DHALF + c], acc);
    }
    float v = silu_f(acc);
    out[idx] = v;
    bf16 h, lo; split_bf16(v, h, lo);
    oh[idx] = h; ol[idx] = lo;
}

// z-half: conv + silu, write split bf16 directly into concat right half
__global__ __launch_bounds__(256)
void conv_z_kernel(const float* __restrict__ xz,
                   const float* __restrict__ w, const float* __restrict__ bias,
                   bf16* __restrict__ cat_h, bf16* __restrict__ cat_l)
{
    int idx = blockIdx.x * blockDim.x + threadIdx.x;
    int c = idx & (DHALF - 1);
    int bl = idx >> 10;
    int l = bl & (LSEQ - 1);
    float acc = bias[c];
    const float* src = xz + (size_t)bl * DINNER + DHALF + c;
    #pragma unroll
    for (int j = 0; j < 4; j++) {
        int ll = l + j - 1;
        if (ll >= 0 && ll < LSEQ)
            acc = fmaf(src[(ptrdiff_t)(j - 1) * DINNER], w[j * DHALF + c], acc);
    }
    float v = silu_f(acc);
    bf16 h, lo; split_bf16(v, h, lo);
    size_t o = (size_t)bl * DINNER + DHALF + c;
    cat_h[o] = h; cat_l[o] = lo;
}

// ---------------------------------------------------------------------------
// Chunk-parallel selective scan.  A[d][n] = -(n+1) => dA_n = exp(-delta)^(n+1).
// Linearity: over a chunk, h_end = exp(-(n+1)*Sum(delta)) * h_start + q,
// where q is the chunk-local state from h_start = 0.
//   Phase 1: per (b, chunk, dblk) compute q and S = Sum(delta).   512 blocks
//   Phase 2: per (b, d) sequential combine over 16 chunks -> h_start.
//   Phase 3: replay each chunk from its h_start, emit y.          512 blocks
// ---------------------------------------------------------------------------
#define PW16(p1, pw)                                                    \
    float p2 = (p1) * (p1), p3 = p2 * (p1), p4 = p2 * p2;               \
    float p5 = p4 * (p1), p6 = p4 * p2, p7 = p4 * p3, p8 = p4 * p4;     \
    float pw[16] = {(p1), p2, p3, p4, p5, p6, p7, p8,                   \
                    p8 * (p1), p8 * p2, p8 * p3, p8 * p4,               \
                    p8 * p5, p8 * p6, p8 * p7, p8 * p8};

__global__ __launch_bounds__(128)
void scan_p1(const float* __restrict__ delta, const float* __restrict__ u,
             const float* __restrict__ xdbl,
             float* __restrict__ q, float* __restrict__ S)
{
    const int tid = threadIdx.x;
    const int chunk = blockIdx.x, dblk = blockIdx.y, b = blockIdx.z;
    const int d = (dblk << 7) + tid;

    __shared__ float sB[16][DSTATE];
    __shared__ float sd[16][128];
    __shared__ float su[16][128];

    float h[DSTATE];
    #pragma unroll
    for (int n = 0; n < DSTATE; n++) h[n] = 0.0f;
    float sum = 0.0f;
    const size_t baseRow = (size_t)b * LSEQ + (size_t)chunk * LCHUNK;

    for (int t0 = 0; t0 < LCHUNK; t0 += 16) {
        {
            int s = tid >> 3;
            int i = (tid & 7) << 1;
            float2 v = *reinterpret_cast<const float2*>(
                xdbl + (baseRow + t0 + s) * XDBL_N + DTRANK + i);
            sB[s][i] = v.x; sB[s][i + 1] = v.y;
        }
        #pragma unroll
        for (int s = 0; s < 16; s++) {
            size_t r = (baseRow + t0 + s) * DHALF + d;
            sd[s][tid] = delta[r];
            su[s][tid] = u[r];
        }
        __syncthreads();

        #pragma unroll
        for (int s = 0; s < 16; s++) {
            float dl = sd[s][tid];
            float du = dl * su[s][tid];
            sum += dl;
            float p1 = __expf(-dl);
            PW16(p1, pw)
            #pragma unroll
            for (int n = 0; n < DSTATE; n++)
                h[n] = fmaf(pw[n], h[n], du * sB[s][n]);
        }
        __syncthreads();
    }
    const size_t cbase = ((size_t)(b * NCHUNK + chunk) * DSTATE) * DHALF + d;
    #pragma unroll
    for (int n = 0; n < DSTATE; n++) q[cbase + (size_t)n * DHALF] = h[n];
    S[(size_t)(b * NCHUNK + chunk) * DHALF + d] = sum;
}

__global__ __launch_bounds__(128)
void scan_p2(const float* __restrict__ q, const float* __restrict__ S,
             float* __restrict__ hs)
{
    const int idx = blockIdx.x * 128 + threadIdx.x;   // < 4096
    const int b = idx >> 10, d = idx & (DHALF - 1);
    float h[DSTATE];
    #pragma unroll
    for (int n = 0; n < DSTATE; n++) h[n] = 0.0f;
    for (int c = 0; c < NCHUNK; c++) {
        const size_t cbase = ((size_t)(b * NCHUNK + c) * DSTATE) * DHALF + d;
        #pragma unroll
        for (int n = 0; n < DSTATE; n++) hs[cbase + (size_t)n * DHALF] = h[n];
        float s = S[(size_t)(b * NCHUNK + c) * DHALF + d];
        float p1 = __expf(-s);
        PW16(p1, pw)
        #pragma unroll
        for (int n = 0; n < DSTATE; n++)
            h[n] = fmaf(pw[n], h[n], q[cbase + (size_t)n * DHALF]);
    }
}

__global__ __launch_bounds__(128)
void scan_p3(const float* __restrict__ delta, const float* __restrict__ u,
             const float* __restrict__ xdbl, const float* __restrict__ hs,
             const float* __restrict__ Dv,
             bf16* __restrict__ cat_h, bf16* __restrict__ cat_l)
{
    const int tid = threadIdx.x;
    const int chunk = blockIdx.x, dblk = blockIdx.y, b = blockIdx.z;
    const int d = (dblk << 7) + tid;

    __shared__ float sB[16][DSTATE];
    __shared__ float sC[16][DSTATE];
    __shared__ float sd[16][128];
    __shared__ float su[16][128];

    float h[DSTATE];
    const size_t cbase = ((size_t)(b * NCHUNK + chunk) * DSTATE) * DHALF + d;
    #pragma unroll
    for (int n = 0; n < DSTATE; n++) h[n] = hs[cbase + (size_t)n * DHALF];
    const float Dd = Dv[d];
    const size_t baseRow = (size_t)b * LSEQ + (size_t)chunk * LCHUNK;

    for (int t0 = 0; t0 < LCHUNK; t0 += 16) {
        {
            int s = tid >> 3;
            int i = (tid & 7) << 2;
            float4 v = *reinterpret_cast<const float4*>(
                xdbl + (baseRow + t0 + s) * XDBL_N + DTRANK + i);
            float vv[4] = {v.x, v.y, v.z, v.w};
            #pragma unroll
            for (int qq = 0; qq < 4; qq++) {
                int ii = i + qq;
                if (ii < DSTATE) sB[s][ii] = vv[qq];
                else             sC[s][ii - DSTATE] = vv[qq];
            }
        }
        #pragma unroll
        for (int s = 0; s < 16; s++) {
            size_t r = (baseRow + t0 + s) * DHALF + d;
            sd[s][tid] = delta[r];
            su[s][tid] = u[r];
        }
        __syncthreads();

        #pragma unroll
        for (int s = 0; s < 16; s++) {
            float dl = sd[s][tid];
            float uu = su[s][tid];
            float du = dl * uu;
            float p1 = __expf(-dl);
            PW16(p1, pw)
            float y0 = 0.f, y1 = 0.f, y2 = 0.f, y3 = 0.f;
            #pragma unroll
            for (int n = 0; n < DSTATE; n += 4) {
                h[n + 0] = fmaf(pw[n + 0], h[n + 0], du * sB[s][n + 0]);
                h[n + 1] = fmaf(pw[n + 1], h[n + 1], du * sB[s][n + 1]);
                h[n + 2] = fmaf(pw[n + 2], h[n + 2], du * sB[s][n + 2]);
                h[n + 3] = fmaf(pw[n + 3], h[n + 3], du * sB[s][n + 3]);
                y0 = fmaf(h[n + 0], sC[s][n + 0], y0);
                y1 = fmaf(h[n + 1], sC[s][n + 1], y1);
                y2 = fmaf(h[n + 2], sC[s][n + 2], y2);
                y3 = fmaf(h[n + 3], sC[s][n + 3], y3);
            }
            float yv = fmaf(uu, Dd, (y0 + y1) + (y2 + y3));
            bf16 hh, ll; split_bf16(yv, hh, ll);
            size_t o = (baseRow + t0 + s) * DINNER + d;
            cat_h[o] = hh; cat_l[o] = ll;
        }
        __syncthreads();
    }
}

// ---------------------------------------------------------------------------
// Launch
// ---------------------------------------------------------------------------
extern "C" void kernel_launch(void* const* d_in, const int* in_sizes, int n_in,
                              void* d_out, int out_size)
{
    const float* x        = (const float*)d_in[0];
    const float* W_in     = (const float*)d_in[1];
    const float* conv_x_w = (const float*)d_in[2];
    const float* conv_x_b = (const float*)d_in[3];
    const float* conv_z_w = (const float*)d_in[4];
    const float* conv_z_b = (const float*)d_in[5];
    const float* W_xdbl   = (const float*)d_in[6];
    const float* W_dt     = (const float*)d_in[7];
    const float* inv_dt   = (const float*)d_in[8];
    const float* Dvec     = (const float*)d_in[9];
    const float* W_out    = (const float*)d_in[10];
    const float* b_out    = (const float*)d_in[11];
    float* out            = (float*)d_out;

    float *p_xz, *p_xs, *p_xdbl, *p_delta, *p_q, *p_hs, *p_S;
    bf16 *p_a1h, *p_a1l, *p_b1h, *p_b1l, *p_xsh, *p_xsl, *p_bxh, *p_bxl;
    bf16 *p_dth, *p_dtl, *p_bdh, *p_bdl, *p_ch, *p_cl, *p_b2h, *p_b2l;
    cudaGetSymbolAddress((void**)&p_xz,    g_xz);
    cudaGetSymbolAddress((void**)&p_xs,    g_xs);
    cudaGetSymbolAddress((void**)&p_xdbl,  g_xdbl);
    cudaGetSymbolAddress((void**)&p_delta, g_delta);
    cudaGetSymbolAddress((void**)&p_q,  g_q);
    cudaGetSymbolAddress((void**)&p_hs, g_hs);
    cudaGetSymbolAddress((void**)&p_S,  g_S);
    cudaGetSymbolAddress((void**)&p_a1h, g_a1h); cudaGetSymbolAddress((void**)&p_a1l, g_a1l);
    cudaGetSymbolAddress((void**)&p_b1h, g_b1h); cudaGetSymbolAddress((void**)&p_b1l, g_b1l);
    cudaGetSymbolAddress((void**)&p_xsh, g_xsh); cudaGetSymbolAddress((void**)&p_xsl, g_xsl);
    cudaGetSymbolAddress((void**)&p_bxh, g_bxh); cudaGetSymbolAddress((void**)&p_bxl, g_bxl);
    cudaGetSymbolAddress((void**)&p_dth, g_dth); cudaGetSymbolAddress((void**)&p_dtl, g_dtl);
    cudaGetSymbolAddress((void**)&p_bdh, g_bdh); cudaGetSymbolAddress((void**)&p_bdl, g_bdl);
    cudaGetSymbolAddress((void**)&p_ch,  g_ch);  cudaGetSymbolAddress((void**)&p_cl,  g_cl);
    cudaGetSymbolAddress((void**)&p_b2h, g_b2h); cudaGetSymbolAddress((void**)&p_b2l, g_b2l);

    constexpr int SMEM128 = 4 * 16384 + 1024;   // 66560
    constexpr int SMEM64  = 4 * 12288 + 1024;   // 50176
    cudaFuncSetAttribute((const void*)gemm_mma<128,false,false,false,false>,
                         cudaFuncAttributeMaxDynamicSharedMemorySize, SMEM128);
    cudaFuncSetAttribute((const void*)gemm_mma<128,true,true,false,false>,
                         cudaFuncAttributeMaxDynamicSharedMemorySize, SMEM128);
    cudaFuncSetAttribute((const void*)gemm_mma<128,false,true,false,false>,
                         cudaFuncAttributeMaxDynamicSharedMemorySize, SMEM128);
    cudaFuncSetAttribute((const void*)gemm_mma<64,false,false,true,true>,
                         cudaFuncAttributeMaxDynamicSharedMemorySize, SMEM64);

    // 1) weight transposes + splits
    tsplit_kernel<<<dim3(DINNER / 32, DMODEL / 32), dim3(32, 8)>>>(W_in,   p_b1h, p_b1l, DMODEL, DINNER);
    tsplit_kernel<<<dim3(XDBL_N / 32, DHALF / 32),  dim3(32, 8)>>>(W_xdbl, p_bxh, p_bxl, DHALF,  XDBL_N);
    tsplit_kernel<<<dim3(DHALF / 32, DTRANK / 32),  dim3(32, 8)>>>(W_dt,   p_bdh, p_bdl, DTRANK, DHALF);
    tsplit_kernel<<<dim3(DMODEL / 32, DINNER / 32), dim3(32, 8)>>>(W_out,  p_b2h, p_b2l, DINNER, DMODEL);

    // 2) split x
    split_kernel<<<(MROWS * DMODEL / 4) / 256, 256>>>(x, p_a1h, p_a1l, MROWS * DMODEL);

    // 3) xz = x @ W_in                              [8192,2048]
    gemm_mma<128,false,false,false,false><<<dim3(DINNER / 128, MROWS / 128), 256, SMEM128>>>(
        p_a1h, p_a1l, p_b1h, p_b1l, nullptr, 0.0f, p_xz, DINNER, DMODEL, DINNER,
        nullptr, nullptr);

    // 4) depthwise convs + silu (x-half also emits split bf16)
    conv_x_kernel<<<(MROWS * DHALF) / 256, 256>>>(p_xz, conv_x_w, conv_x_b,
                                                  p_xs, p_xsh, p_xsl);
    conv_z_kernel<<<(MROWS * DHALF) / 256, 256>>>(p_xz, conv_z_w, conv_z_b, p_ch, p_cl);

    // 5) x_dbl = xs @ W_xdbl  [8192,96]; epilogue also splits dt cols [0,64)
    gemm_mma<64,false,false,true,true><<<dim3(1, MROWS / 64), 256, SMEM64>>>(
        p_xsh, p_xsl, p_bxh, p_bxl, nullptr, 0.0f, p_xdbl, XDBL_N, DHALF, XDBL_N,
        p_dth, p_dtl);

    // 6) delta = softplus(dt_low @ W_dt + 2*inv_dt) [8192,1024]
    gemm_mma<128,true,true,false,false><<<dim3(DHALF / 128, MROWS / 128), 256, SMEM128>>>(
        p_dth, p_dtl, p_bdh, p_bdl, inv_dt, 2.0f, p_delta, DHALF, DTRANK, DHALF,
        nullptr, nullptr);

    // 7) chunk-parallel selective scan -> concat left half (split bf16)
    scan_p1<<<dim3(NCHUNK, 8, B_SZ), 128>>>(p_delta, p_xs, p_xdbl, p_q, p_S);
    scan_p2<<<32, 128>>>(p_q, p_S, p_hs);
    scan_p3<<<dim3(NCHUNK, 8, B_SZ), 128>>>(p_delta, p_xs, p_xdbl, p_hs, Dvec, p_ch, p_cl);

    // 8) out = [y|z] @ W_out + b_out                [8192,1024]
    gemm_mma<128,false,true,false,false><<<dim3(DMODEL / 128, MROWS / 128), 256, SMEM128>>>(
        p_ch, p_cl, p_b2h, p_b2l, b_out, 1.0f, out, DMODEL, DINNER, DMODEL,
        nullptr, nullptr);
}

// round 5
// speedup vs baseline: 3.9720x; 1.2584x over previous
#include <cuda_runtime.h>
#include <cuda_fp16.h>
#include <cstdint>
#include <cstddef>

// ---------------------------------------------------------------------------
// Problem constants (MambaVisionMixer, B=4, L=2048)
// ---------------------------------------------------------------------------
#define B_SZ    4
#define LSEQ    2048
#define DMODEL  1024
#define DINNER  2048
#define DHALF   1024
#define DSTATE  16
#define DTRANK  64
#define XDBL_N  96
#define MROWS   (B_SZ*LSEQ)   // 8192
#define NCHUNK  16
#define LCHUNK  (LSEQ/NCHUNK) // 128

typedef __half h16;

// ---------------------------------------------------------------------------
// Device scratch (static __device__ arrays — no allocations)
// ---------------------------------------------------------------------------
__device__ float g_xz   [(size_t)MROWS * DINNER];   // 64 MB
__device__ float g_xs   [(size_t)MROWS * DHALF];    // 32 MB
__device__ float g_xdbl [(size_t)MROWS * XDBL_N];   // 3 MB
__device__ float g_delta[(size_t)MROWS * DHALF];    // 32 MB

__device__ float g_q [(size_t)B_SZ * NCHUNK * DSTATE * DHALF];  // 4 MB
__device__ float g_hs[(size_t)B_SZ * NCHUNK * DSTATE * DHALF];  // 4 MB
__device__ float g_S [(size_t)B_SZ * NCHUNK * DHALF];           // 256 KB

__device__ h16 g_a1h[(size_t)MROWS * DMODEL];      // x hi
__device__ h16 g_a1l[(size_t)MROWS * DMODEL];      // x lo
__device__ h16 g_b1h[(size_t)DINNER * DMODEL];     // W_in^T hi  [2048,1024]
__device__ h16 g_b1l[(size_t)DINNER * DMODEL];     // (unused by 2-stream; kept)
__device__ h16 g_xsh[(size_t)MROWS * DHALF];       // xs hi
__device__ h16 g_xsl[(size_t)MROWS * DHALF];
__device__ h16 g_bxh[(size_t)XDBL_N * DHALF];      // W_xdbl^T [96,1024]
__device__ h16 g_bxl[(size_t)XDBL_N * DHALF];
__device__ h16 g_dth[(size_t)MROWS * DTRANK];      // dt_low hi [8192,64]
__device__ h16 g_dtl[(size_t)MROWS * DTRANK];
__device__ h16 g_bdh[(size_t)DHALF * DTRANK];      // W_dt^T [1024,64]
__device__ h16 g_bdl[(size_t)DHALF * DTRANK];
__device__ h16 g_ch [(size_t)MROWS * DINNER];      // [y|z] hi [8192,2048]
__device__ h16 g_cl [(size_t)MROWS * DINNER];
__device__ h16 g_b2h[(size_t)DMODEL * DINNER];     // W_out^T [1024,2048]
__device__ h16 g_b2l[(size_t)DMODEL * DINNER];     // (unused by 2-stream; kept)

// ---------------------------------------------------------------------------
// Helpers (sm_80-era ISA only: compiles at compute_103 non-'a' target)
// ---------------------------------------------------------------------------
__device__ __forceinline__ uint32_t smem_u32(const void* p) {
    uint32_t r;
    asm("{ .reg .u64 t; cvta.to.shared.u64 t, %1; cvt.u32.u64 %0, t; }"
        : "=r"(r) : "l"(p));
    return r;
}

#define CP16(dst, src) \
    asm volatile("cp.async.cg.shared.global [%0], [%1], 16;" \
        :: "r"(dst), "l"(src) : "memory")
#define CP16Z(dst, src, sz) \
    asm volatile("cp.async.cg.shared.global [%0], [%1], 16, %2;" \
        :: "r"(dst), "l"(src), "r"(sz) : "memory")
#define CP_COMMIT() asm volatile("cp.async.commit_group;" ::: "memory")
#define CP_WAIT2()  asm volatile("cp.async.wait_group 2;" ::: "memory")

__device__ __forceinline__ void ldsm4(uint32_t* r, uint32_t addr) {
    asm volatile("ldmatrix.sync.aligned.m8n8.x4.shared.b16 {%0,%1,%2,%3}, [%4];"
        : "=r"(r[0]), "=r"(r[1]), "=r"(r[2]), "=r"(r[3]) : "r"(addr));
}

__device__ __forceinline__ void mma16816(float* d, const uint32_t* a,
                                         const uint32_t* b) {
    asm volatile(
        "mma.sync.aligned.m16n8k16.row.col.f32.f16.f16.f32 "
        "{%0,%1,%2,%3}, {%4,%5,%6,%7}, {%8,%9}, {%0,%1,%2,%3};"
        : "+f"(d[0]), "+f"(d[1]), "+f"(d[2]), "+f"(d[3])
        : "r"(a[0]), "r"(a[1]), "r"(a[2]), "r"(a[3]), "r"(b[0]), "r"(b[1]));
}

__device__ __forceinline__ float softplus_f(float x) {
    return fmaxf(x, 0.0f) + log1pf(expf(-fabsf(x)));
}
__device__ __forceinline__ float silu_f(float x) {
    return x / (1.0f + expf(-x));
}
__device__ __forceinline__ void split_h16(float v, h16& h, h16& l) {
    h = __float2half_rn(v);
    l = __float2half_rn(v - __half2float(h));
}

// ---------------------------------------------------------------------------
// Tensor-core GEMM (mma.sync fp16, fp32 accum) with fp16-split emulation.
//   C[M,N] = A[M,K] @ B^T   (B stored [N,K] row-major)
//   NSTREAM==2: streams (Ahi,Bhi), (Alo,Bhi)   -> error ~ A*Blo ~ 2^-12
//   NSTREAM==3: streams (Ahi,Bhi), (Ahi,Blo), (Alo,Bhi) -> error ~ 2^-22
//   CTA BMx128, 8 warps (2x4), warp tile (BM/2)x32, BK=32, 4-stage cp.async.
//   Smem rows 64B; XOR swizzle c ^= (row>>1)&3 -> conflict-free ldmatrix.
//   DTSPLIT: additionally write fp16 hi/lo of cols [0,64) to dth/dtl.
// ---------------------------------------------------------------------------
template <int BM, int NSTREAM, bool SOFTPLUS, bool HASBIAS, bool NCHK, bool DTSPLIT>
__global__ __launch_bounds__(256, 2)
void gemm_mma(const h16* __restrict__ Ahi, const h16* __restrict__ Alo,
              const h16* __restrict__ Bhi, const h16* __restrict__ Blo,
              const float* __restrict__ bias, float bias_scale,
              float* __restrict__ C, int N, int K, int Brows,
              h16* __restrict__ dth, h16* __restrict__ dtl)
{
    constexpr int MI    = BM / 32;          // m-iterations per warp
    constexpr int ABYTES = BM * 64;
    constexpr int STAGE = ABYTES + 8192;
    extern __shared__ char dsm[];
    const uint32_t base = (smem_u32(dsm) + 1023u) & ~1023u;

    const int tid    = threadIdx.x;
    const int rowBlk = blockIdx.y * BM;
    const int colBlk = blockIdx.x * 128;
    const int wid    = tid >> 5;
    const int lane   = tid & 31;
    const int warp_m = wid >> 2;          // 0..1 -> BM/2 rows
    const int warp_n = wid & 3;           // 0..3 -> 32 cols
    const int mat    = lane >> 3;
    const int rin    = lane & 7;

    const int KC     = K / 32;
    const int CHUNKS = NSTREAM * KC;

    uint32_t offA[MI][2], offB[2][2];
    #pragma unroll
    for (int mi = 0; mi < MI; mi++)
        #pragma unroll
        for (int j = 0; j < 2; j++) {
            int row = warp_m * (BM / 2) + mi * 16 + (mat & 1) * 8 + rin;
            int c   = 2 * j + (mat >> 1);
            offA[mi][j] = row * 64 + ((c ^ ((row >> 1) & 3)) << 4);
        }
    #pragma unroll
    for (int bi = 0; bi < 2; bi++)
        #pragma unroll
        for (int j = 0; j < 2; j++) {
            int row = warp_n * 32 + bi * 16 + (mat >> 1) * 8 + rin;
            int c   = 2 * j + (mat & 1);
            offB[bi][j] = ABYTES + row * 64 + ((c ^ ((row >> 1) & 3)) << 4);
        }

    float acc[MI][4][4];
    #pragma unroll
    for (int i = 0; i < MI; i++)
        #pragma unroll
        for (int j = 0; j < 4; j++)
            #pragma unroll
            for (int q = 0; q < 4; q++) acc[i][j][q] = 0.0f;

    auto load_stage = [&](int s, int c) {
        int stream = (c >= 2 * KC) ? 2 : ((c >= KC) ? 1 : 0);
        int k0 = (c - stream * KC) * 32;
        const h16* Ap;
        const h16* Bp;
        if (NSTREAM == 2) {
            Ap = stream ? Alo : Ahi;
            Bp = Bhi;
        } else {
            Ap = (stream == 2) ? Alo : Ahi;
            Bp = (stream == 1) ? Blo : Bhi;
        }
        uint32_t as_ = base + s * STAGE;
        uint32_t bs_ = as_ + ABYTES;
        #pragma unroll
        for (int t = 0; t < BM / 64; t++) {
            int idx = tid + t * 256;
            int r = idx >> 2, cc = idx & 3;
            uint32_t dst = as_ + r * 64 + ((cc ^ ((r >> 1) & 3)) << 4);
            const char* src =
                (const char*)(Ap + (size_t)(rowBlk + r) * K + k0) + cc * 16;
            CP16(dst, src);
        }
        #pragma unroll
        for (int t = 0; t < 2; t++) {
            int idx = tid + t * 256;
            int r = idx >> 2, cc = idx & 3;
            uint32_t dst = bs_ + r * 64 + ((cc ^ ((r >> 1) & 3)) << 4);
            if (NCHK) {
                int br = colBlk + r;
                int ok = (br < Brows);
                const char* src =
                    (const char*)(Bp + (size_t)(ok ? br : 0) * K + k0) + cc * 16;
                CP16Z(dst, src, ok ? 16u : 0u);
            } else {
                const char* src =
                    (const char*)(Bp + (size_t)(colBlk + r) * K + k0) + cc * 16;
                CP16(dst, src);
            }
        }
    };

    #pragma unroll
    for (int s = 0; s < 3; s++) { load_stage(s, s); CP_COMMIT(); }

    for (int i = 0; i < CHUNKS; i++) {
        CP_WAIT2();
        __syncthreads();
        if (i + 3 < CHUNKS) load_stage((i + 3) & 3, i + 3);
        CP_COMMIT();

        const uint32_t sb = base + (i & 3) * STAGE;
        #pragma unroll
        for (int j = 0; j < 2; j++) {
            uint32_t Af[MI][4];
            #pragma unroll
            for (int mi = 0; mi < MI; mi++) ldsm4(Af[mi], sb + offA[mi][j]);
            uint32_t Bf[4][2];
            #pragma unroll
            for (int bi = 0; bi < 2; bi++) {
                uint32_t r[4];
                ldsm4(r, sb + offB[bi][j]);
                Bf[bi * 2 + 0][0] = r[0]; Bf[bi * 2 + 0][1] = r[1];
                Bf[bi * 2 + 1][0] = r[2]; Bf[bi * 2 + 1][1] = r[3];
            }
            #pragma unroll
            for (int mi = 0; mi < MI; mi++)
                #pragma unroll
                for (int ni = 0; ni < 4; ni++)
                    mma16816(acc[mi][ni], Af[mi], Bf[ni]);
        }
    }

    // epilogue
    const int mrow = rowBlk + warp_m * (BM / 2) + (lane >> 2);
    const int ncol = colBlk + warp_n * 32 + (lane & 3) * 2;
    #pragma unroll
    for (int mi = 0; mi < MI; mi++) {
        #pragma unroll
        for (int ni = 0; ni < 4; ni++) {
            int n0 = ncol + ni * 8;
            if (NCHK && n0 >= Brows) continue;
            float v0 = acc[mi][ni][0], v1 = acc[mi][ni][1];
            float v2 = acc[mi][ni][2], v3 = acc[mi][ni][3];
            if (HASBIAS) {
                float b0 = bias_scale * __ldg(bias + n0);
                float b1 = bias_scale * __ldg(bias + n0 + 1);
                v0 += b0; v1 += b1; v2 += b0; v3 += b1;
            }
            if (SOFTPLUS) {
                v0 = softplus_f(v0); v1 = softplus_f(v1);
                v2 = softplus_f(v2); v3 = softplus_f(v3);
            }
            size_t r0 = (size_t)(mrow + mi * 16) * N + n0;
            size_t r1 = (size_t)(mrow + mi * 16 + 8) * N + n0;
            *reinterpret_cast<float2*>(C + r0) = make_float2(v0, v1);
            *reinterpret_cast<float2*>(C + r1) = make_float2(v2, v3);
            if (DTSPLIT && n0 < DTRANK) {
                h16 hh, ll;
                size_t d0 = (size_t)(mrow + mi * 16) * DTRANK + n0;
                size_t d1 = (size_t)(mrow + mi * 16 + 8) * DTRANK + n0;
                split_h16(v0, hh, ll); dth[d0] = hh;     dtl[d0] = ll;
                split_h16(v1, hh, ll); dth[d0 + 1] = hh; dtl[d0 + 1] = ll;
                split_h16(v2, hh, ll); dth[d1] = hh;     dtl[d1] = ll;
                split_h16(v3, hh, ll); dth[d1 + 1] = hh; dtl[d1 + 1] = ll;
            }
        }
    }
}

// ---------------------------------------------------------------------------
// fp32 -> fp16 hi/lo split (contiguous)
// ---------------------------------------------------------------------------
__global__ __launch_bounds__(256)
void split_kernel(const float* __restrict__ in, h16* __restrict__ oh,
                  h16* __restrict__ ol, int n)
{
    int i = (blockIdx.x * blockDim.x + threadIdx.x) * 4;
    if (i >= n) return;
    float4 v = *reinterpret_cast<const float4*>(in + i);
    h16 h0, l0, h1, l1, h2, l2, h3, l3;
    split_h16(v.x, h0, l0); split_h16(v.y, h1, l1);
    split_h16(v.z, h2, l2); split_h16(v.w, h3, l3);
    __half2* ph = reinterpret_cast<__half2*>(oh + i);
    __half2* pl = reinterpret_cast<__half2*>(ol + i);
    ph[0] = __half2(h0, h1); ph[1] = __half2(h2, h3);
    pl[0] = __half2(l0, l1); pl[1] = __half2(l2, l3);
}

// transpose + split:  in [R,C] fp32 -> out [C,R] fp16 hi/lo
__global__ __launch_bounds__(256)
void tsplit_kernel(const float* __restrict__ in, h16* __restrict__ oh,
                   h16* __restrict__ ol, int R, int C)
{
    __shared__ float t[32][33];
    const int cx = blockIdx.x * 32, ry = blockIdx.y * 32;
    const int tx = threadIdx.x, ty = threadIdx.y;   // 32 x 8
    #pragma unroll
    for (int j = ty; j < 32; j += 8)
        t[j][tx] = in[(size_t)(ry + j) * C + cx + tx];
    __syncthreads();
    #pragma unroll
    for (int j = ty; j < 32; j += 8) {
        float v = t[tx][j];
        h16 h, l; split_h16(v, h, l);
        size_t o = (size_t)(cx + j) * R + ry + tx;
        oh[o] = h; ol[o] = l;
    }
}

// ---------------------------------------------------------------------------
// Depthwise conv (k=4, SAME: pad left 1, right 2) + SiLU
// x-half: writes fp32 (scan input) AND split fp16 (xdbl GEMM input)
// ---------------------------------------------------------------------------
__global__ __launch_bounds__(256)
void conv_x_kernel(const float* __restrict__ xz,
                   const float* __restrict__ w, const float* __restrict__ bias,
                   float* __restrict__ out,
                   h16* __restrict__ oh, h16* __restrict__ ol)
{
    int idx = blockIdx.x * blockDim.x + threadIdx.x;
    int c = idx & (DHALF - 1);
    int bl = idx >> 10;
    int l = bl & (LSEQ - 1);
    float acc = bias[c];
    const float* src = xz + (size_t)bl * DINNER + c;
    #pragma unroll
    for (int j = 0; j < 4; j++) {
        int ll = l + j - 1;
        if (ll >= 0 && ll < LSEQ)
            acc = fmaf(src[(ptrdiff_t)(j - 1) * DINNER], w[j * DHALF + c], acc);
    }
    float v = silu_f(acc);
    out[idx] = v;
    h16 h, lo; split_h16(v, h, lo);
    oh[idx] = h; ol[idx] = lo;
}

// z-half: conv + silu, write split fp16 directly into concat right half
__global__ __launch_bounds__(256)
void conv_z_kernel(const float* __restrict__ xz,
                   const float* __restrict__ w, const float* __restrict__ bias,
                   h16* __restrict__ cat_h, h16* __restrict__ cat_l)
{
    int idx = blockIdx.x * blockDim.x + threadIdx.x;
    int c = idx & (DHALF - 1);
    int bl = idx >> 10;
    int l = bl & (LSEQ - 1);
    float acc = bias[c];
    const float* src = xz + (size_t)bl * DINNER + DHALF + c;
    #pragma unroll
    for (int j = 0; j < 4; j++) {
        int ll = l + j - 1;
        if (ll >= 0 && ll < LSEQ)
            acc = fmaf(src[(ptrdiff_t)(j - 1) * DINNER], w[j * DHALF + c], acc);
    }
    float v = silu_f(acc);
    h16 h, lo; split_h16(v, h, lo);
    size_t o = (size_t)bl * DINNER + DHALF + c;
    cat_h[o] = h; cat_l[o] = lo;
}

// ---------------------------------------------------------------------------
// Chunk-parallel selective scan.  A[d][n] = -(n+1) => dA_n = exp(-delta)^(n+1).
//   Phase 1: per (b, chunk, dblk) compute q and S = Sum(delta).   512 blocks
//   Phase 2: per (b, d) sequential combine over 16 chunks -> h_start.
//   Phase 3: replay each chunk from its h_start, emit y.          512 blocks
// ---------------------------------------------------------------------------
#define PW16(p1, pw)                                                    \
    float p2 = (p1) * (p1), p3 = p2 * (p1), p4 = p2 * p2;               \
    float p5 = p4 * (p1), p6 = p4 * p2, p7 = p4 * p3, p8 = p4 * p4;     \
    float pw[16] = {(p1), p2, p3, p4, p5, p6, p7, p8,                   \
                    p8 * (p1), p8 * p2, p8 * p3, p8 * p4,               \
                    p8 * p5, p8 * p6, p8 * p7, p8 * p8};

__global__ __launch_bounds__(128)
void scan_p1(const float* __restrict__ delta, const float* __restrict__ u,
             const float* __restrict__ xdbl,
             float* __restrict__ q, float* __restrict__ S)
{
    const int tid = threadIdx.x;
    const int chunk = blockIdx.x, dblk = blockIdx.y, b = blockIdx.z;
    const int d = (dblk << 7) + tid;

    __shared__ float sB[16][DSTATE];
    __shared__ float sd[16][128];
    __shared__ float su[16][128];

    float h[DSTATE];
    #pragma unroll
    for (int n = 0; n < DSTATE; n++) h[n] = 0.0f;
    float sum = 0.0f;
    const size_t baseRow = (size_t)b * LSEQ + (size_t)chunk * LCHUNK;

    for (int t0 = 0; t0 < LCHUNK; t0 += 16) {
        {
            int s = tid >> 3;
            int i = (tid & 7) << 1;
            float2 v = *reinterpret_cast<const float2*>(
                xdbl + (baseRow + t0 + s) * XDBL_N + DTRANK + i);
            sB[s][i] = v.x; sB[s][i + 1] = v.y;
        }
        #pragma unroll
        for (int s = 0; s < 16; s++) {
            size_t r = (baseRow + t0 + s) * DHALF + d;
            sd[s][tid] = delta[r];
            su[s][tid] = u[r];
        }
        __syncthreads();

        #pragma unroll
        for (int s = 0; s < 16; s++) {
            float dl = sd[s][tid];
            float du = dl * su[s][tid];
            sum += dl;
            float p1 = __expf(-dl);
            PW16(p1, pw)
            #pragma unroll
            for (int n = 0; n < DSTATE; n++)
                h[n] = fmaf(pw[n], h[n], du * sB[s][n]);
        }
        __syncthreads();
    }
    const size_t cbase = ((size_t)(b * NCHUNK + chunk) * DSTATE) * DHALF + d;
    #pragma unroll
    for (int n = 0; n < DSTATE; n++) q[cbase + (size_t)n * DHALF] = h[n];
    S[(size_t)(b * NCHUNK + chunk) * DHALF + d] = sum;
}

__global__ __launch_bounds__(128)
void scan_p2(const float* __restrict__ q, const float* __restrict__ S,
             float* __restrict__ hs)
{
    const int idx = blockIdx.x * 128 + threadIdx.x;   // < 4096
    const int b = idx >> 10, d = idx & (DHALF - 1);
    float h[DSTATE];
    #pragma unroll
    for (int n = 0; n < DSTATE; n++) h[n] = 0.0f;
    for (int c = 0; c < NCHUNK; c++) {
        const size_t cbase = ((size_t)(b * NCHUNK + c) * DSTATE) * DHALF + d;
        #pragma unroll
        for (int n = 0; n < DSTATE; n++) hs[cbase + (size_t)n * DHALF] = h[n];
        float s = S[(size_t)(b * NCHUNK + c) * DHALF + d];
        float p1 = __expf(-s);
        PW16(p1, pw)
        #pragma unroll
        for (int n = 0; n < DSTATE; n++)
            h[n] = fmaf(pw[n], h[n], q[cbase + (size_t)n * DHALF]);
    }
}

__global__ __launch_bounds__(128)
void scan_p3(const float* __restrict__ delta, const float* __restrict__ u,
             const float* __restrict__ xdbl, const float* __restrict__ hs,
             const float* __restrict__ Dv,
             h16* __restrict__ cat_h, h16* __restrict__ cat_l)
{
    const int tid = threadIdx.x;
    const int chunk = blockIdx.x, dblk = blockIdx.y, b = blockIdx.z;
    const int d = (dblk << 7) + tid;

    __shared__ float sB[16][DSTATE];
    __shared__ float sC[16][DSTATE];
    __shared__ float sd[16][128];
    __shared__ float su[16][128];

    float h[DSTATE];
    const size_t cbase = ((size_t)(b * NCHUNK + chunk) * DSTATE) * DHALF + d;
    #pragma unroll
    for (int n = 0; n < DSTATE; n++) h[n] = hs[cbase + (size_t)n * DHALF];
    const float Dd = Dv[d];
    const size_t baseRow = (size_t)b * LSEQ + (size_t)chunk * LCHUNK;

    for (int t0 = 0; t0 < LCHUNK; t0 += 16) {
        {
            int s = tid >> 3;
            int i = (tid & 7) << 2;
            float4 v = *reinterpret_cast<const float4*>(
                xdbl + (baseRow + t0 + s) * XDBL_N + DTRANK + i);
            float vv[4] = {v.x, v.y, v.z, v.w};
            #pragma unroll
            for (int qq = 0; qq < 4; qq++) {
                int ii = i + qq;
                if (ii < DSTATE) sB[s][ii] = vv[qq];
                else             sC[s][ii - DSTATE] = vv[qq];
            }
        }
        #pragma unroll
        for (int s = 0; s < 16; s++) {
            size_t r = (baseRow + t0 + s) * DHALF + d;
            sd[s][tid] = delta[r];
            su[s][tid] = u[r];
        }
        __syncthreads();

        #pragma unroll
        for (int s = 0; s < 16; s++) {
            float dl = sd[s][tid];
            float uu = su[s][tid];
            float du = dl * uu;
            float p1 = __expf(-dl);
            PW16(p1, pw)
            float y0 = 0.f, y1 = 0.f, y2 = 0.f, y3 = 0.f;
            #pragma unroll
            for (int n = 0; n < DSTATE; n += 4) {
                h[n + 0] = fmaf(pw[n + 0], h[n + 0], du * sB[s][n + 0]);
                h[n + 1] = fmaf(pw[n + 1], h[n + 1], du * sB[s][n + 1]);
                h[n + 2] = fmaf(pw[n + 2], h[n + 2], du * sB[s][n + 2]);
                h[n + 3] = fmaf(pw[n + 3], h[n + 3], du * sB[s][n + 3]);
                y0 = fmaf(h[n + 0], sC[s][n + 0], y0);
                y1 = fmaf(h[n + 1], sC[s][n + 1], y1);
                y2 = fmaf(h[n + 2], sC[s][n + 2], y2);
                y3 = fmaf(h[n + 3], sC[s][n + 3], y3);
            }
            float yv = fmaf(uu, Dd, (y0 + y1) + (y2 + y3));
            h16 hh, ll; split_h16(yv, hh, ll);
            size_t o = (baseRow + t0 + s) * DINNER + d;
            cat_h[o] = hh; cat_l[o] = ll;
        }
        __syncthreads();
    }
}

// ---------------------------------------------------------------------------
// Launch
// ---------------------------------------------------------------------------
extern "C" void kernel_launch(void* const* d_in, const int* in_sizes, int n_in,
                              void* d_out, int out_size)
{
    const float* x        = (const float*)d_in[0];
    const float* W_in     = (const float*)d_in[1];
    const float* conv_x_w = (const float*)d_in[2];
    const float* conv_x_b = (const float*)d_in[3];
    const float* conv_z_w = (const float*)d_in[4];
    const float* conv_z_b = (const float*)d_in[5];
    const float* W_xdbl   = (const float*)d_in[6];
    const float* W_dt     = (const float*)d_in[7];
    const float* inv_dt   = (const float*)d_in[8];
    const float* Dvec     = (const float*)d_in[9];
    const float* W_out    = (const float*)d_in[10];
    const float* b_out    = (const float*)d_in[11];
    float* out            = (float*)d_out;

    float *p_xz, *p_xs, *p_xdbl, *p_delta, *p_q, *p_hs, *p_S;
    h16 *p_a1h, *p_a1l, *p_b1h, *p_b1l, *p_xsh, *p_xsl, *p_bxh, *p_bxl;
    h16 *p_dth, *p_dtl, *p_bdh, *p_bdl, *p_ch, *p_cl, *p_b2h, *p_b2l;
    cudaGetSymbolAddress((void**)&p_xz,    g_xz);
    cudaGetSymbolAddress((void**)&p_xs,    g_xs);
    cudaGetSymbolAddress((void**)&p_xdbl,  g_xdbl);
    cudaGetSymbolAddress((void**)&p_delta, g_delta);
    cudaGetSymbolAddress((void**)&p_q,  g_q);
    cudaGetSymbolAddress((void**)&p_hs, g_hs);
    cudaGetSymbolAddress((void**)&p_S,  g_S);
    cudaGetSymbolAddress((void**)&p_a1h, g_a1h); cudaGetSymbolAddress((void**)&p_a1l, g_a1l);
    cudaGetSymbolAddress((void**)&p_b1h, g_b1h); cudaGetSymbolAddress((void**)&p_b1l, g_b1l);
    cudaGetSymbolAddress((void**)&p_xsh, g_xsh); cudaGetSymbolAddress((void**)&p_xsl, g_xsl);
    cudaGetSymbolAddress((void**)&p_bxh, g_bxh); cudaGetSymbolAddress((void**)&p_bxl, g_bxl);
    cudaGetSymbolAddress((void**)&p_dth, g_dth); cudaGetSymbolAddress((void**)&p_dtl, g_dtl);
    cudaGetSymbolAddress((void**)&p_bdh, g_bdh); cudaGetSymbolAddress((void**)&p_bdl, g_bdl);
    cudaGetSymbolAddress((void**)&p_ch,  g_ch);  cudaGetSymbolAddress((void**)&p_cl,  g_cl);
    cudaGetSymbolAddress((void**)&p_b2h, g_b2h); cudaGetSymbolAddress((void**)&p_b2l, g_b2l);

    constexpr int SMEM128 = 4 * 16384 + 1024;   // 66560
    constexpr int SMEM64  = 4 * 12288 + 1024;   // 50176
    cudaFuncSetAttribute((const void*)gemm_mma<128,2,false,false,false,false>,
                         cudaFuncAttributeMaxDynamicSharedMemorySize, SMEM128);
    cudaFuncSetAttribute((const void*)gemm_mma<128,3,true,true,false,false>,
                         cudaFuncAttributeMaxDynamicSharedMemorySize, SMEM128);
    cudaFuncSetAttribute((const void*)gemm_mma<128,2,false,true,false,false>,
                         cudaFuncAttributeMaxDynamicSharedMemorySize, SMEM128);
    cudaFuncSetAttribute((const void*)gemm_mma<64,3,false,false,true,true>,
                         cudaFuncAttributeMaxDynamicSharedMemorySize, SMEM64);

    // 1) weight transposes + splits
    tsplit_kernel<<<dim3(DINNER / 32, DMODEL / 32), dim3(32, 8)>>>(W_in,   p_b1h, p_b1l, DMODEL, DINNER);
    tsplit_kernel<<<dim3(XDBL_N / 32, DHALF / 32),  dim3(32, 8)>>>(W_xdbl, p_bxh, p_bxl, DHALF,  XDBL_N);
    tsplit_kernel<<<dim3(DHALF / 32, DTRANK / 32),  dim3(32, 8)>>>(W_dt,   p_bdh, p_bdl, DTRANK, DHALF);
    tsplit_kernel<<<dim3(DMODEL / 32, DINNER / 32), dim3(32, 8)>>>(W_out,  p_b2h, p_b2l, DINNER, DMODEL);

    // 2) split x
    split_kernel<<<(MROWS * DMODEL / 4) / 256, 256>>>(x, p_a1h, p_a1l, MROWS * DMODEL);

    // 3) xz = x @ W_in                              [8192,2048]  (2-stream)
    gemm_mma<128,2,false,false,false,false><<<dim3(DINNER / 128, MROWS / 128), 256, SMEM128>>>(
        p_a1h, p_a1l, p_b1h, p_b1l, nullptr, 0.0f, p_xz, DINNER, DMODEL, DINNER,
        nullptr, nullptr);

    // 4) depthwise convs + silu (x-half also emits split fp16)
    conv_x_kernel<<<(MROWS * DHALF) / 256, 256>>>(p_xz, conv_x_w, conv_x_b,
                                                  p_xs, p_xsh, p_xsl);
    conv_z_kernel<<<(MROWS * DHALF) / 256, 256>>>(p_xz, conv_z_w, conv_z_b, p_ch, p_cl);

    // 5) x_dbl = xs @ W_xdbl  [8192,96] (3-stream; feeds B/C/dt — keep clean)
    gemm_mma<64,3,false,false,true,true><<<dim3(1, MROWS / 64), 256, SMEM64>>>(
        p_xsh, p_xsl, p_bxh, p_bxl, nullptr, 0.0f, p_xdbl, XDBL_N, DHALF, XDBL_N,
        p_dth, p_dtl);

    // 6) delta = softplus(dt_low @ W_dt + 2*inv_dt) [8192,1024] (3-stream)
    gemm_mma<128,3,true,true,false,false><<<dim3(DHALF / 128, MROWS / 128), 256, SMEM128>>>(
        p_dth, p_dtl, p_bdh, p_bdl, inv_dt, 2.0f, p_delta, DHALF, DTRANK, DHALF,
        nullptr, nullptr);

    // 7) chunk-parallel selective scan -> concat left half (split fp16)
    scan_p1<<<dim3(NCHUNK, 8, B_SZ), 128>>>(p_delta, p_xs, p_xdbl, p_q, p_S);
    scan_p2<<<32, 128>>>(p_q, p_S, p_hs);
    scan_p3<<<dim3(NCHUNK, 8, B_SZ), 128>>>(p_delta, p_xs, p_xdbl, p_hs, Dvec, p_ch, p_cl);

    // 8) out = [y|z] @ W_out + b_out                [8192,1024]  (2-stream)
    gemm_mma<128,2,false,true,false,false><<<dim3(DMODEL / 128, MROWS / 128), 256, SMEM128>>>(
        p_ch, p_cl, p_b2h, p_b2l, b_out, 1.0f, out, DMODEL, DINNER, DMODEL,
        nullptr, nullptr);
}

// round 6
// speedup vs baseline: 4.4295x; 1.1152x over previous
#include <cuda_runtime.h>
#include <cuda_fp16.h>
#include <cstdint>
#include <cstddef>

// ---------------------------------------------------------------------------
// Problem constants (MambaVisionMixer, B=4, L=2048)
// ---------------------------------------------------------------------------
#define B_SZ    4
#define LSEQ    2048
#define DMODEL  1024
#define DINNER  2048
#define DHALF   1024
#define DSTATE  16
#define DTRANK  64
#define XDBL_N  96
#define MROWS   (B_SZ*LSEQ)   // 8192
#define NCHUNK  16
#define LCHUNK  (LSEQ/NCHUNK) // 128

typedef __half h16;

// ---------------------------------------------------------------------------
// Device scratch (static __device__ arrays — no allocations)
// ---------------------------------------------------------------------------
__device__ float g_xz   [(size_t)MROWS * DINNER];   // 64 MB
__device__ float g_xdbl [(size_t)MROWS * XDBL_N];   // 3 MB
__device__ float g_delta[(size_t)MROWS * DHALF];    // 32 MB

__device__ float g_q [(size_t)B_SZ * NCHUNK * DSTATE * DHALF];  // 4 MB
__device__ float g_hs[(size_t)B_SZ * NCHUNK * DSTATE * DHALF];  // 4 MB
__device__ float g_S [(size_t)B_SZ * NCHUNK * DHALF];           // 256 KB

__device__ h16 g_a1h[(size_t)MROWS * DMODEL];      // x hi
__device__ h16 g_a1l[(size_t)MROWS * DMODEL];      // x lo
__device__ h16 g_b1h[(size_t)DINNER * DMODEL];     // W_in^T hi  [2048,1024]
__device__ h16 g_b1l[(size_t)DINNER * DMODEL];     // (unused by 2-stream)
__device__ h16 g_xsh[(size_t)MROWS * DHALF];       // xs hi
__device__ h16 g_xsl[(size_t)MROWS * DHALF];       // xs lo
__device__ h16 g_bxh[(size_t)XDBL_N * DHALF];      // W_xdbl^T [96,1024]
__device__ h16 g_bxl[(size_t)XDBL_N * DHALF];
__device__ h16 g_dth[(size_t)MROWS * DTRANK];      // dt_low hi [8192,64]
__device__ h16 g_dtl[(size_t)MROWS * DTRANK];
__device__ h16 g_bdh[(size_t)DHALF * DTRANK];      // W_dt^T [1024,64]
__device__ h16 g_bdl[(size_t)DHALF * DTRANK];
__device__ h16 g_ch [(size_t)MROWS * DINNER];      // [y|z] hi [8192,2048]
__device__ h16 g_cl [(size_t)MROWS * DINNER];
__device__ h16 g_b2h[(size_t)DMODEL * DINNER];     // W_out^T [1024,2048]
__device__ h16 g_b2l[(size_t)DMODEL * DINNER];     // (unused by 2-stream)

// ---------------------------------------------------------------------------
// Helpers (sm_80-era ISA only: compiles at compute_103 non-'a' target)
// ---------------------------------------------------------------------------
__device__ __forceinline__ uint32_t smem_u32(const void* p) {
    uint32_t r;
    asm("{ .reg .u64 t; cvta.to.shared.u64 t, %1; cvt.u32.u64 %0, t; }"
        : "=r"(r) : "l"(p));
    return r;
}

#define CP16(dst, src) \
    asm volatile("cp.async.cg.shared.global [%0], [%1], 16;" \
        :: "r"(dst), "l"(src) : "memory")
#define CP16Z(dst, src, sz) \
    asm volatile("cp.async.cg.shared.global [%0], [%1], 16, %2;" \
        :: "r"(dst), "l"(src), "r"(sz) : "memory")
#define CP_COMMIT() asm volatile("cp.async.commit_group;" ::: "memory")
#define CP_WAIT2()  asm volatile("cp.async.wait_group 2;" ::: "memory")

__device__ __forceinline__ void ldsm4(uint32_t* r, uint32_t addr) {
    asm volatile("ldmatrix.sync.aligned.m8n8.x4.shared.b16 {%0,%1,%2,%3}, [%4];"
        : "=r"(r[0]), "=r"(r[1]), "=r"(r[2]), "=r"(r[3]) : "r"(addr));
}

__device__ __forceinline__ void mma16816(float* d, const uint32_t* a,
                                         const uint32_t* b) {
    asm volatile(
        "mma.sync.aligned.m16n8k16.row.col.f32.f16.f16.f32 "
        "{%0,%1,%2,%3}, {%4,%5,%6,%7}, {%8,%9}, {%0,%1,%2,%3};"
        : "+f"(d[0]), "+f"(d[1]), "+f"(d[2]), "+f"(d[3])
        : "r"(a[0]), "r"(a[1]), "r"(a[2]), "r"(a[3]), "r"(b[0]), "r"(b[1]));
}

__device__ __forceinline__ float softplus_f(float x) {
    return fmaxf(x, 0.0f) + log1pf(expf(-fabsf(x)));
}
__device__ __forceinline__ float silu_f(float x) {
    return x / (1.0f + expf(-x));
}
__device__ __forceinline__ void split_h16(float v, h16& h, h16& l) {
    h = __float2half_rn(v);
    l = __float2half_rn(v - __half2float(h));
}

// ---------------------------------------------------------------------------
// Tensor-core GEMM (mma.sync fp16, fp32 accum) with fp16-split emulation.
//   C[M,N] = A[M,K] @ B^T   (B stored [N,K] row-major)
//   NSTREAM==2: streams (Ahi,Bhi), (Alo,Bhi)   -> error ~ A*Blo ~ 2^-12
//   NSTREAM==3: streams (Ahi,Bhi), (Ahi,Blo), (Alo,Bhi) -> error ~ 2^-22
//   CTA BMx128, 8 warps (2x4), warp tile (BM/2)x32.
//   BK=64: stage = BM*128B (A) + 128*128B (B); 3-stage cp.async pipeline.
//   Smem rows 128B; SW128 swizzle chunk c ^= row&7 -> conflict-free ldmatrix.
//   DTSPLIT: additionally write fp16 hi/lo of cols [0,64) to dth/dtl.
// ---------------------------------------------------------------------------
template <int BM, int NSTREAM, bool SOFTPLUS, bool HASBIAS, bool NCHK, bool DTSPLIT>
__global__ __launch_bounds__(256, 2)
void gemm_mma(const h16* __restrict__ Ahi, const h16* __restrict__ Alo,
              const h16* __restrict__ Bhi, const h16* __restrict__ Blo,
              const float* __restrict__ bias, float bias_scale,
              float* __restrict__ C, int N, int K, int Brows,
              h16* __restrict__ dth, h16* __restrict__ dtl)
{
    constexpr int MI     = BM / 32;          // m-iterations per warp
    constexpr int ABYTES = BM * 128;
    constexpr int STAGE  = ABYTES + 128 * 128;
    extern __shared__ char dsm[];
    const uint32_t base = (smem_u32(dsm) + 1023u) & ~1023u;

    const int tid    = threadIdx.x;
    const int rowBlk = blockIdx.y * BM;
    const int colBlk = blockIdx.x * 128;
    const int wid    = tid >> 5;
    const int lane   = tid & 31;
    const int warp_m = wid >> 2;          // 0..1 -> BM/2 rows
    const int warp_n = wid & 3;           // 0..3 -> 32 cols
    const int mat    = lane >> 3;
    const int rin    = lane & 7;

    const int KC     = K / 64;
    const int CHUNKS = NSTREAM * KC;

    // ldmatrix offsets, rows are 128B (64 halves), c = 16B chunk index 0..7
    uint32_t offA[MI][4], offB[2][4];
    #pragma unroll
    for (int mi = 0; mi < MI; mi++)
        #pragma unroll
        for (int j = 0; j < 4; j++) {
            int row = warp_m * (BM / 2) + mi * 16 + (mat & 1) * 8 + rin;
            int c   = 2 * j + (mat >> 1);
            offA[mi][j] = row * 128 + ((c ^ (row & 7)) << 4);
        }
    #pragma unroll
    for (int bi = 0; bi < 2; bi++)
        #pragma unroll
        for (int j = 0; j < 4; j++) {
            int row = warp_n * 32 + bi * 16 + (mat >> 1) * 8 + rin;
            int c   = 2 * j + (mat & 1);
            offB[bi][j] = ABYTES + row * 128 + ((c ^ (row & 7)) << 4);
        }

    float acc[MI][4][4];
    #pragma unroll
    for (int i = 0; i < MI; i++)
        #pragma unroll
        for (int j = 0; j < 4; j++)
            #pragma unroll
            for (int q = 0; q < 4; q++) acc[i][j][q] = 0.0f;

    auto load_stage = [&](int s, int c) {
        int stream = (c >= 2 * KC) ? 2 : ((c >= KC) ? 1 : 0);
        int k0 = (c - stream * KC) * 64;
        const h16* Ap;
        const h16* Bp;
        if (NSTREAM == 2) {
            Ap = stream ? Alo : Ahi;
            Bp = Bhi;
        } else {
            Ap = (stream == 2) ? Alo : Ahi;
            Bp = (stream == 1) ? Blo : Bhi;
        }
        uint32_t as_ = base + s * STAGE;
        uint32_t bs_ = as_ + ABYTES;
        #pragma unroll
        for (int t = 0; t < BM / 32; t++) {          // BM rows x 8 chunks
            int idx = tid + t * 256;
            int r = idx >> 3, cc = idx & 7;
            uint32_t dst = as_ + r * 128 + ((cc ^ (r & 7)) << 4);
            const char* src =
                (const char*)(Ap + (size_t)(rowBlk + r) * K + k0) + cc * 16;
            CP16(dst, src);
        }
        #pragma unroll
        for (int t = 0; t < 4; t++) {                // 128 rows x 8 chunks
            int idx = tid + t * 256;
            int r = idx >> 3, cc = idx & 7;
            uint32_t dst = bs_ + r * 128 + ((cc ^ (r & 7)) << 4);
            if (NCHK) {
                int br = colBlk + r;
                int ok = (br < Brows);
                const char* src =
                    (const char*)(Bp + (size_t)(ok ? br : 0) * K + k0) + cc * 16;
                CP16Z(dst, src, ok ? 16u : 0u);
            } else {
                const char* src =
                    (const char*)(Bp + (size_t)(colBlk + r) * K + k0) + cc * 16;
                CP16(dst, src);
            }
        }
    };

    // prologue: fill 3 stages (CHUNKS >= 3 always: min is 3-stream K=64)
    #pragma unroll
    for (int s = 0; s < 3; s++) { load_stage(s, s); CP_COMMIT(); }

    int slot = 0;
    #pragma unroll 1
    for (int i = 0; i < CHUNKS; i++) {
        CP_WAIT2();              // stage i landed (2 newer groups pending)
        __syncthreads();
        const uint32_t sb = base + slot * STAGE;
        #pragma unroll
        for (int j = 0; j < 4; j++) {
            uint32_t Af[MI][4];
            #pragma unroll
            for (int mi = 0; mi < MI; mi++) ldsm4(Af[mi], sb + offA[mi][j]);
            uint32_t Bf[4][2];
            #pragma unroll
            for (int bi = 0; bi < 2; bi++) {
                uint32_t r[4];
                ldsm4(r, sb + offB[bi][j]);
                Bf[bi * 2 + 0][0] = r[0]; Bf[bi * 2 + 0][1] = r[1];
                Bf[bi * 2 + 1][0] = r[2]; Bf[bi * 2 + 1][1] = r[3];
            }
            #pragma unroll
            for (int mi = 0; mi < MI; mi++)
                #pragma unroll
                for (int ni = 0; ni < 4; ni++)
                    mma16816(acc[mi][ni], Af[mi], Bf[ni]);
        }
        __syncthreads();         // all warps done reading slot
        if (i + 3 < CHUNKS) load_stage(slot, i + 3);
        CP_COMMIT();
        slot = (slot == 2) ? 0 : slot + 1;
    }

    // epilogue
    const int mrow = rowBlk + warp_m * (BM / 2) + (lane >> 2);
    const int ncol = colBlk + warp_n * 32 + (lane & 3) * 2;
    #pragma unroll
    for (int mi = 0; mi < MI; mi++) {
        #pragma unroll
        for (int ni = 0; ni < 4; ni++) {
            int n0 = ncol + ni * 8;
            if (NCHK && n0 >= Brows) continue;
            float v0 = acc[mi][ni][0], v1 = acc[mi][ni][1];
            float v2 = acc[mi][ni][2], v3 = acc[mi][ni][3];
            if (HASBIAS) {
                float b0 = bias_scale * __ldg(bias + n0);
                float b1 = bias_scale * __ldg(bias + n0 + 1);
                v0 += b0; v1 += b1; v2 += b0; v3 += b1;
            }
            if (SOFTPLUS) {
                v0 = softplus_f(v0); v1 = softplus_f(v1);
                v2 = softplus_f(v2); v3 = softplus_f(v3);
            }
            size_t r0 = (size_t)(mrow + mi * 16) * N + n0;
            size_t r1 = (size_t)(mrow + mi * 16 + 8) * N + n0;
            *reinterpret_cast<float2*>(C + r0) = make_float2(v0, v1);
            *reinterpret_cast<float2*>(C + r1) = make_float2(v2, v3);
            if (DTSPLIT && n0 < DTRANK) {
                h16 hh, ll;
                size_t d0 = (size_t)(mrow + mi * 16) * DTRANK + n0;
                size_t d1 = (size_t)(mrow + mi * 16 + 8) * DTRANK + n0;
                split_h16(v0, hh, ll); dth[d0] = hh;     dtl[d0] = ll;
                split_h16(v1, hh, ll); dth[d0 + 1] = hh; dtl[d0 + 1] = ll;
                split_h16(v2, hh, ll); dth[d1] = hh;     dtl[d1] = ll;
                split_h16(v3, hh, ll); dth[d1 + 1] = hh; dtl[d1 + 1] = ll;
            }
        }
    }
}

// ---------------------------------------------------------------------------
// fp32 -> fp16 hi/lo split (contiguous)
// ---------------------------------------------------------------------------
__global__ __launch_bounds__(256)
void split_kernel(const float* __restrict__ in, h16* __restrict__ oh,
                  h16* __restrict__ ol, int n)
{
    int i = (blockIdx.x * blockDim.x + threadIdx.x) * 4;
    if (i >= n) return;
    float4 v = *reinterpret_cast<const float4*>(in + i);
    h16 h0, l0, h1, l1, h2, l2, h3, l3;
    split_h16(v.x, h0, l0); split_h16(v.y, h1, l1);
    split_h16(v.z, h2, l2); split_h16(v.w, h3, l3);
    __half2* ph = reinterpret_cast<__half2*>(oh + i);
    __half2* pl = reinterpret_cast<__half2*>(ol + i);
    ph[0] = __half2(h0, h1); ph[1] = __half2(h2, h3);
    pl[0] = __half2(l0, l1); pl[1] = __half2(l2, l3);
}

// transpose + split:  in [R,C] fp32 -> out [C,R] fp16 hi/lo
__global__ __launch_bounds__(256)
void tsplit_kernel(const float* __restrict__ in, h16* __restrict__ oh,
                   h16* __restrict__ ol, int R, int C)
{
    __shared__ float t[32][33];
    const int cx = blockIdx.x * 32, ry = blockIdx.y * 32;
    const int tx = threadIdx.x, ty = threadIdx.y;   // 32 x 8
    #pragma unroll
    for (int j = ty; j < 32; j += 8)
        t[j][tx] = in[(size_t)(ry + j) * C + cx + tx];
    __syncthreads();
    #pragma unroll
    for (int j = ty; j < 32; j += 8) {
        float v = t[tx][j];
        h16 h, l; split_h16(v, h, l);
        size_t o = (size_t)(cx + j) * R + ry + tx;
        oh[o] = h; ol[o] = l;
    }
}

// ---------------------------------------------------------------------------
// Depthwise conv (k=4, SAME: pad left 1, right 2) + SiLU
// x-half: writes split fp16 only (scan reconstructs u = hi + lo)
// ---------------------------------------------------------------------------
__global__ __launch_bounds__(256)
void conv_x_kernel(const float* __restrict__ xz,
                   const float* __restrict__ w, const float* __restrict__ bias,
                   h16* __restrict__ oh, h16* __restrict__ ol)
{
    int idx = blockIdx.x * blockDim.x + threadIdx.x;
    int c = idx & (DHALF - 1);
    int bl = idx >> 10;
    int l = bl & (LSEQ - 1);
    float acc = bias[c];
    const float* src = xz + (size_t)bl * DINNER + c;
    #pragma unroll
    for (int j = 0; j < 4; j++) {
        int ll = l + j - 1;
        if (ll >= 0 && ll < LSEQ)
            acc = fmaf(src[(ptrdiff_t)(j - 1) * DINNER], w[j * DHALF + c], acc);
    }
    float v = silu_f(acc);
    h16 h, lo; split_h16(v, h, lo);
    oh[idx] = h; ol[idx] = lo;
}

// z-half: conv + silu, write split fp16 directly into concat right half
__global__ __launch_bounds__(256)
void conv_z_kernel(const float* __restrict__ xz,
                   const float* __restrict__ w, const float* __restrict__ bias,
                   h16* __restrict__ cat_h, h16* __restrict__ cat_l)
{
    int idx = blockIdx.x * blockDim.x + threadIdx.x;
    int c = idx & (DHALF - 1);
    int bl = idx >> 10;
    int l = bl & (LSEQ - 1);
    float acc = bias[c];
    const float* src = xz + (size_t)bl * DINNER + DHALF + c;
    #pragma unroll
    for (int j = 0; j < 4; j++) {
        int ll = l + j - 1;
        if (ll >= 0 && ll < LSEQ)
            acc = fmaf(src[(ptrdiff_t)(j - 1) * DINNER], w[j * DHALF + c], acc);
    }
    float v = silu_f(acc);
    h16 h, lo; split_h16(v, h, lo);
    size_t o = (size_t)bl * DINNER + DHALF + c;
    cat_h[o] = h; cat_l[o] = lo;
}

// ---------------------------------------------------------------------------
// Chunk-parallel selective scan.  A[d][n] = -(n+1) => dA_n = exp(-delta)^(n+1).
//   Phase 1: per (b, chunk, dblk) compute q and S = Sum(delta).   512 blocks
//   Phase 2: per (b, d) sequential combine over 16 chunks -> h_start.
//   Phase 3: replay each chunk from its h_start, emit y.          512 blocks
// u is reconstructed from the fp16 split pair (exact to 2^-22).
// ---------------------------------------------------------------------------
#define PW16(p1, pw)                                                    \
    float p2 = (p1) * (p1), p3 = p2 * (p1), p4 = p2 * p2;               \
    float p5 = p4 * (p1), p6 = p4 * p2, p7 = p4 * p3, p8 = p4 * p4;     \
    float pw[16] = {(p1), p2, p3, p4, p5, p6, p7, p8,                   \
                    p8 * (p1), p8 * p2, p8 * p3, p8 * p4,               \
                    p8 * p5, p8 * p6, p8 * p7, p8 * p8};

__global__ __launch_bounds__(128)
void scan_p1(const float* __restrict__ delta,
             const h16* __restrict__ uh, const h16* __restrict__ ul,
             const float* __restrict__ xdbl,
             float* __restrict__ q, float* __restrict__ S)
{
    const int tid = threadIdx.x;
    const int chunk = blockIdx.x, dblk = blockIdx.y, b = blockIdx.z;
    const int d = (dblk << 7) + tid;

    __shared__ float sB[16][DSTATE];
    __shared__ float sd[16][128];
    __shared__ float su[16][128];

    float h[DSTATE];
    #pragma unroll
    for (int n = 0; n < DSTATE; n++) h[n] = 0.0f;
    float sum = 0.0f;
    const size_t baseRow = (size_t)b * LSEQ + (size_t)chunk * LCHUNK;

    for (int t0 = 0; t0 < LCHUNK; t0 += 16) {
        {
            int s = tid >> 3;
            int i = (tid & 7) << 1;
            float2 v = *reinterpret_cast<const float2*>(
                xdbl + (baseRow + t0 + s) * XDBL_N + DTRANK + i);
            sB[s][i] = v.x; sB[s][i + 1] = v.y;
        }
        #pragma unroll
        for (int s = 0; s < 16; s++) {
            size_t r = (baseRow + t0 + s) * DHALF + d;
            sd[s][tid] = delta[r];
            su[s][tid] = __half2float(uh[r]) + __half2float(ul[r]);
        }
        __syncthreads();

        #pragma unroll
        for (int s = 0; s < 16; s++) {
            float dl = sd[s][tid];
            float du = dl * su[s][tid];
            sum += dl;
            float p1 = __expf(-dl);
            PW16(p1, pw)
            #pragma unroll
            for (int n = 0; n < DSTATE; n++)
                h[n] = fmaf(pw[n], h[n], du * sB[s][n]);
        }
        __syncthreads();
    }
    const size_t cbase = ((size_t)(b * NCHUNK + chunk) * DSTATE) * DHALF + d;
    #pragma unroll
    for (int n = 0; n < DSTATE; n++) q[cbase + (size_t)n * DHALF] = h[n];
    S[(size_t)(b * NCHUNK + chunk) * DHALF + d] = sum;
}

__global__ __launch_bounds__(128)
void scan_p2(const float* __restrict__ q, const float* __restrict__ S,
             float* __restrict__ hs)
{
    const int idx = blockIdx.x * 128 + threadIdx.x;   // < 4096
    const int b = idx >> 10, d = idx & (DHALF - 1);
    float h[DSTATE];
    #pragma unroll
    for (int n = 0; n < DSTATE; n++) h[n] = 0.0f;
    for (int c = 0; c < NCHUNK; c++) {
        const size_t cbase = ((size_t)(b * NCHUNK + c) * DSTATE) * DHALF + d;
        #pragma unroll
        for (int n = 0; n < DSTATE; n++) hs[cbase + (size_t)n * DHALF] = h[n];
        float s = S[(size_t)(b * NCHUNK + c) * DHALF + d];
        float p1 = __expf(-s);
        PW16(p1, pw)
        #pragma unroll
        for (int n = 0; n < DSTATE; n++)
            h[n] = fmaf(pw[n], h[n], q[cbase + (size_t)n * DHALF]);
    }
}

__global__ __launch_bounds__(128)
void scan_p3(const float* __restrict__ delta,
             const h16* __restrict__ uh, const h16* __restrict__ ul,
             const float* __restrict__ xdbl, const float* __restrict__ hs,
             const float* __restrict__ Dv,
             h16* __restrict__ cat_h, h16* __restrict__ cat_l)
{
    const int tid = threadIdx.x;
    const int chunk = blockIdx.x, dblk = blockIdx.y, b = blockIdx.z;
    const int d = (dblk << 7) + tid;

    __shared__ float sB[16][DSTATE];
    __shared__ float sC[16][DSTATE];
    __shared__ float sd[16][128];
    __shared__ float su[16][128];

    float h[DSTATE];
    const size_t cbase = ((size_t)(b * NCHUNK + chunk) * DSTATE) * DHALF + d;
    #pragma unroll
    for (int n = 0; n < DSTATE; n++) h[n] = hs[cbase + (size_t)n * DHALF];
    const float Dd = Dv[d];
    const size_t baseRow = (size_t)b * LSEQ + (size_t)chunk * LCHUNK;

    for (int t0 = 0; t0 < LCHUNK; t0 += 16) {
        {
            int s = tid >> 3;
            int i = (tid & 7) << 2;
            float4 v = *reinterpret_cast<const float4*>(
                xdbl + (baseRow + t0 + s) * XDBL_N + DTRANK + i);
            float vv[4] = {v.x, v.y, v.z, v.w};
            #pragma unroll
            for (int qq = 0; qq < 4; qq++) {
                int ii = i + qq;
                if (ii < DSTATE) sB[s][ii] = vv[qq];
                else             sC[s][ii - DSTATE] = vv[qq];
            }
        }
        #pragma unroll
        for (int s = 0; s < 16; s++) {
            size_t r = (baseRow + t0 + s) * DHALF + d;
            sd[s][tid] = delta[r];
            su[s][tid] = __half2float(uh[r]) + __half2float(ul[r]);
        }
        __syncthreads();

        #pragma unroll
        for (int s = 0; s < 16; s++) {
            float dl = sd[s][tid];
            float uu = su[s][tid];
            float du = dl * uu;
            float p1 = __expf(-dl);
            PW16(p1, pw)
            float y0 = 0.f, y1 = 0.f, y2 = 0.f, y3 = 0.f;
            #pragma unroll
            for (int n = 0; n < DSTATE; n += 4) {
                h[n + 0] = fmaf(pw[n + 0], h[n + 0], du * sB[s][n + 0]);
                h[n + 1] = fmaf(pw[n + 1], h[n + 1], du * sB[s][n + 1]);
                h[n + 2] = fmaf(pw[n + 2], h[n + 2], du * sB[s][n + 2]);
                h[n + 3] = fmaf(pw[n + 3], h[n + 3], du * sB[s][n + 3]);
                y0 = fmaf(h[n + 0], sC[s][n + 0], y0);
                y1 = fmaf(h[n + 1], sC[s][n + 1], y1);
                y2 = fmaf(h[n + 2], sC[s][n + 2], y2);
                y3 = fmaf(h[n + 3], sC[s][n + 3], y3);
            }
            float yv = fmaf(uu, Dd, (y0 + y1) + (y2 + y3));
            h16 hh, ll; split_h16(yv, hh, ll);
            size_t o = (baseRow + t0 + s) * DINNER + d;
            cat_h[o] = hh; cat_l[o] = ll;
        }
        __syncthreads();
    }
}

// ---------------------------------------------------------------------------
// Launch
// ---------------------------------------------------------------------------
extern "C" void kernel_launch(void* const* d_in, const int* in_sizes, int n_in,
                              void* d_out, int out_size)
{
    const float* x        = (const float*)d_in[0];
    const float* W_in     = (const float*)d_in[1];
    const float* conv_x_w = (const float*)d_in[2];
    const float* conv_x_b = (const float*)d_in[3];
    const float* conv_z_w = (const float*)d_in[4];
    const float* conv_z_b = (const float*)d_in[5];
    const float* W_xdbl   = (const float*)d_in[6];
    const float* W_dt     = (const float*)d_in[7];
    const float* inv_dt   = (const float*)d_in[8];
    const float* Dvec     = (const float*)d_in[9];
    const float* W_out    = (const float*)d_in[10];
    const float* b_out    = (const float*)d_in[11];
    float* out            = (float*)d_out;

    float *p_xz, *p_xdbl, *p_delta, *p_q, *p_hs, *p_S;
    h16 *p_a1h, *p_a1l, *p_b1h, *p_b1l, *p_xsh, *p_xsl, *p_bxh, *p_bxl;
    h16 *p_dth, *p_dtl, *p_bdh, *p_bdl, *p_ch, *p_cl, *p_b2h, *p_b2l;
    cudaGetSymbolAddress((void**)&p_xz,    g_xz);
    cudaGetSymbolAddress((void**)&p_xdbl,  g_xdbl);
    cudaGetSymbolAddress((void**)&p_delta, g_delta);
    cudaGetSymbolAddress((void**)&p_q,  g_q);
    cudaGetSymbolAddress((void**)&p_hs, g_hs);
    cudaGetSymbolAddress((void**)&p_S,  g_S);
    cudaGetSymbolAddress((void**)&p_a1h, g_a1h); cudaGetSymbolAddress((void**)&p_a1l, g_a1l);
    cudaGetSymbolAddress((void**)&p_b1h, g_b1h); cudaGetSymbolAddress((void**)&p_b1l, g_b1l);
    cudaGetSymbolAddress((void**)&p_xsh, g_xsh); cudaGetSymbolAddress((void**)&p_xsl, g_xsl);
    cudaGetSymbolAddress((void**)&p_bxh, g_bxh); cudaGetSymbolAddress((void**)&p_bxl, g_bxl);
    cudaGetSymbolAddress((void**)&p_dth, g_dth); cudaGetSymbolAddress((void**)&p_dtl, g_dtl);
    cudaGetSymbolAddress((void**)&p_bdh, g_bdh); cudaGetSymbolAddress((void**)&p_bdl, g_bdl);
    cudaGetSymbolAddress((void**)&p_ch,  g_ch);  cudaGetSymbolAddress((void**)&p_cl,  g_cl);
    cudaGetSymbolAddress((void**)&p_b2h, g_b2h); cudaGetSymbolAddress((void**)&p_b2l, g_b2l);

    constexpr int SMEM128 = 3 * (128 * 128 + 128 * 128) + 1024;   // 99328
    constexpr int SMEM64  = 3 * (64 * 128 + 128 * 128) + 1024;    // 74752
    cudaFuncSetAttribute((const void*)gemm_mma<128,2,false,false,false,false>,
                         cudaFuncAttributeMaxDynamicSharedMemorySize, SMEM128);
    cudaFuncSetAttribute((const void*)gemm_mma<128,3,true,true,false,false>,
                         cudaFuncAttributeMaxDynamicSharedMemorySize, SMEM128);
    cudaFuncSetAttribute((const void*)gemm_mma<128,2,false,true,false,false>,
                         cudaFuncAttributeMaxDynamicSharedMemorySize, SMEM128);
    cudaFuncSetAttribute((const void*)gemm_mma<64,3,false,false,true,true>,
                         cudaFuncAttributeMaxDynamicSharedMemorySize, SMEM64);

    // 1) weight transposes + splits
    tsplit_kernel<<<dim3(DINNER / 32, DMODEL / 32), dim3(32, 8)>>>(W_in,   p_b1h, p_b1l, DMODEL, DINNER);
    tsplit_kernel<<<dim3(XDBL_N / 32, DHALF / 32),  dim3(32, 8)>>>(W_xdbl, p_bxh, p_bxl, DHALF,  XDBL_N);
    tsplit_kernel<<<dim3(DHALF / 32, DTRANK / 32),  dim3(32, 8)>>>(W_dt,   p_bdh, p_bdl, DTRANK, DHALF);
    tsplit_kernel<<<dim3(DMODEL / 32, DINNER / 32), dim3(32, 8)>>>(W_out,  p_b2h, p_b2l, DINNER, DMODEL);

    // 2) split x
    split_kernel<<<(MROWS * DMODEL / 4) / 256, 256>>>(x, p_a1h, p_a1l, MROWS * DMODEL);

    // 3) xz = x @ W_in                              [8192,2048]  (2-stream)
    gemm_mma<128,2,false,false,false,false><<<dim3(DINNER / 128, MROWS / 128), 256, SMEM128>>>(
        p_a1h, p_a1l, p_b1h, p_b1l, nullptr, 0.0f, p_xz, DINNER, DMODEL, DINNER,
        nullptr, nullptr);

    // 4) depthwise convs + silu (split fp16 outputs)
    conv_x_kernel<<<(MROWS * DHALF) / 256, 256>>>(p_xz, conv_x_w, conv_x_b, p_xsh, p_xsl);
    conv_z_kernel<<<(MROWS * DHALF) / 256, 256>>>(p_xz, conv_z_w, conv_z_b, p_ch, p_cl);

    // 5) x_dbl = xs @ W_xdbl  [8192,96] (3-stream; feeds B/C/dt — keep clean)
    gemm_mma<64,3,false,false,true,true><<<dim3(1, MROWS / 64), 256, SMEM64>>>(
        p_xsh, p_xsl, p_bxh, p_bxl, nullptr, 0.0f, p_xdbl, XDBL_N, DHALF, XDBL_N,
        p_dth, p_dtl);

    // 6) delta = softplus(dt_low @ W_dt + 2*inv_dt) [8192,1024] (3-stream)
    gemm_mma<128,3,true,true,false,false><<<dim3(DHALF / 128, MROWS / 128), 256, SMEM128>>>(
        p_dth, p_dtl, p_bdh, p_bdl, inv_dt, 2.0f, p_delta, DHALF, DTRANK, DHALF,
        nullptr, nullptr);

    // 7) chunk-parallel selective scan -> concat left half (split fp16)
    scan_p1<<<dim3(NCHUNK, 8, B_SZ), 128>>>(p_delta, p_xsh, p_xsl, p_xdbl, p_q, p_S);
    scan_p2<<<32, 128>>>(p_q, p_S, p_hs);
    scan_p3<<<dim3(NCHUNK, 8, B_SZ), 128>>>(p_delta, p_xsh, p_xsl, p_xdbl, p_hs, Dvec, p_ch, p_cl);

    // 8) out = [y|z] @ W_out + b_out                [8192,1024]  (2-stream)
    gemm_mma<128,2,false,true,false,false><<<dim3(DMODEL / 128, MROWS / 128), 256, SMEM128>>>(
        p_ch, p_cl, p_b2h, p_b2l, b_out, 1.0f, out, DMODEL, DINNER, DMODEL,
        nullptr, nullptr);
}